// round 13
// baseline (speedup 1.0000x reference)
#include <cuda_runtime.h>
#include <cuda_bf16.h>
#include <math.h>
#include <stdint.h>

// Problem constants (fixed shapes)
constexpr int Bsz  = 2;
constexpr int Sseq = 2048;
constexpr int Fdim = 1024;
constexpr int Hh   = 16;
constexpr int Dh   = 64;
constexpr int Mrows = Bsz * Sseq;   // 4096

// Scratch (device globals, allocation-free). All operands live as TWO bf16
// planes: hi = bf16(x), mid = bf16(x - hi). hi+mid recovers fp32 to ~2^-16.
__device__ __nv_bfloat16 g_Afh[(size_t)Mrows * Fdim];
__device__ __nv_bfloat16 g_Afm[(size_t)Mrows * Fdim];
__device__ __nv_bfloat16 g_Ath[(size_t)Mrows * Fdim];
__device__ __nv_bfloat16 g_Atm[(size_t)Mrows * Fdim];
__device__ __nv_bfloat16 g_Wqh[(size_t)Fdim * Fdim];      // w_q^T  [n][k]
__device__ __nv_bfloat16 g_Wqm[(size_t)Fdim * Fdim];
__device__ __nv_bfloat16 g_Wkvh[(size_t)2 * Fdim * Fdim]; // w_kv^T [n][k]
__device__ __nv_bfloat16 g_Wkvm[(size_t)2 * Fdim * Fdim];
__device__ __nv_bfloat16 g_Woh[(size_t)Fdim * Fdim];      // w_out^T [n][k]
__device__ __nv_bfloat16 g_Wom[(size_t)Fdim * Fdim];
__device__ __nv_bfloat16 g_Qh[(size_t)Mrows * Fdim];
__device__ __nv_bfloat16 g_Qm[(size_t)Mrows * Fdim];
__device__ __nv_bfloat16 g_Kh[(size_t)Mrows * Fdim];
__device__ __nv_bfloat16 g_Km[(size_t)Mrows * Fdim];
__device__ __nv_bfloat16 g_Vth[(size_t)Mrows * Fdim];     // V^T [b][h][d][s]
__device__ __nv_bfloat16 g_Vtm[(size_t)Mrows * Fdim];
__device__ __nv_bfloat16 g_Oh[(size_t)Mrows * Fdim];
__device__ __nv_bfloat16 g_Om[(size_t)Mrows * Fdim];

// ---------------------------------------------------------------------------
// PTX helpers
// ---------------------------------------------------------------------------
__device__ __forceinline__ void cp_async16(uint32_t saddr, const void* gptr) {
    asm volatile("cp.async.cg.shared.global [%0], [%1], 16;"
                 :: "r"(saddr), "l"(gptr));
}
__device__ __forceinline__ void cp_commit() {
    asm volatile("cp.async.commit_group;");
}
__device__ __forceinline__ void cp_wait0() {
    asm volatile("cp.async.wait_group 0;");
}
__device__ __forceinline__ void cp_wait1() {
    asm volatile("cp.async.wait_group 1;");
}

__device__ __forceinline__ void mma_bf16(
    float& d0, float& d1, float& d2, float& d3,
    uint32_t a0, uint32_t a1, uint32_t a2, uint32_t a3,
    uint32_t b0, uint32_t b1)
{
    asm volatile(
        "mma.sync.aligned.m16n8k16.row.col.f32.bf16.bf16.f32 "
        "{%0,%1,%2,%3},{%4,%5,%6,%7},{%8,%9},{%0,%1,%2,%3};"
        : "+f"(d0), "+f"(d1), "+f"(d2), "+f"(d3)
        : "r"(a0), "r"(a1), "r"(a2), "r"(a3), "r"(b0), "r"(b1));
}

__device__ __forceinline__ void bsplit(float v, __nv_bfloat16& h, __nv_bfloat16& m) {
    h = __float2bfloat16_rn(v);
    m = __float2bfloat16_rn(v - __bfloat162float(h));
}
__device__ __forceinline__ uint32_t bpack(__nv_bfloat16 lo, __nv_bfloat16 hi) {
    __nv_bfloat162 t;
    t.x = lo; t.y = hi;
    return *reinterpret_cast<uint32_t*>(&t);
}

// ---------------------------------------------------------------------------
// Pre-pass: elementwise split (no transpose) for activations [M][K].
// ---------------------------------------------------------------------------
__global__ __launch_bounds__(256) void asplit_kernel(
    const float* __restrict__ src, __nv_bfloat16* __restrict__ hi,
    __nv_bfloat16* __restrict__ mid, int n4)
{
    const int i = blockIdx.x * 256 + threadIdx.x;
    if (i >= n4) return;
    float4 v = ((const float4*)src)[i];
    __nv_bfloat16 h0, h1, h2, h3, m0, m1, m2, m3;
    bsplit(v.x, h0, m0); bsplit(v.y, h1, m1);
    bsplit(v.z, h2, m2); bsplit(v.w, h3, m3);
    ((uint2*)hi)[i]  = make_uint2(bpack(h0, h1), bpack(h2, h3));
    ((uint2*)mid)[i] = make_uint2(bpack(m0, m1), bpack(m2, m3));
}

// Pre-pass: split + transpose weights w[k][n] -> planes [n][k].
__global__ __launch_bounds__(256) void wsplit_kernel(
    const float* __restrict__ w, __nv_bfloat16* __restrict__ th,
    __nv_bfloat16* __restrict__ tm, int K, int N)
{
    __shared__ float ts[32][33];
    const int k0 = blockIdx.x * 32;
    const int n0 = blockIdx.y * 32;
    const int tx = threadIdx.x & 31;
    const int ty = threadIdx.x >> 5;
    #pragma unroll
    for (int i = 0; i < 4; i++)
        ts[ty + 8 * i][tx] = w[(size_t)(k0 + ty + 8 * i) * N + n0 + tx];
    __syncthreads();
    #pragma unroll
    for (int i = 0; i < 4; i++) {
        float v = ts[tx][ty + 8 * i];
        __nv_bfloat16 h, m;
        bsplit(v, h, m);
        const size_t o = (size_t)(n0 + ty + 8 * i) * K + k0 + tx;
        th[o] = h;
        tm[o] = m;
    }
}

// Row-0 fix: fully-masked row -> uniform softmax -> mean of V rows.
__global__ __launch_bounds__(256) void row0_kernel(
    const __nv_bfloat16* __restrict__ Vth, const __nv_bfloat16* __restrict__ Vtm,
    __nv_bfloat16* __restrict__ Oh, __nv_bfloat16* __restrict__ Om)
{
    __shared__ float red[256];
    const int f = blockIdx.x;
    const int b = blockIdx.y;
    const int h = f >> 6, d = f & 63;
    const size_t base = ((size_t)(b * 16 + h) * 64 + d) * 2048;
    float s = 0.f;
    for (int i = threadIdx.x; i < 2048; i += 256)
        s += __bfloat162float(Vth[base + i]) + __bfloat162float(Vtm[base + i]);
    red[threadIdx.x] = s;
    __syncthreads();
    for (int o = 128; o > 0; o >>= 1) {
        if (threadIdx.x < o) red[threadIdx.x] += red[threadIdx.x + o];
        __syncthreads();
    }
    if (threadIdx.x == 0) {
        const float v = red[0] * (1.f / 2048.f);
        __nv_bfloat16 hh, mm;
        bsplit(v, hh, mm);
        const size_t o = (size_t)(b * Sseq) * 1024 + f;
        Oh[o] = hh;
        Om[o] = mm;
    }
}

// ---------------------------------------------------------------------------
// bf16x3 GEMM core: C[M,N] = A[M,1024] @ W^T[n][k] (+bias via epilogue).
// CTA tile 128x256, BK=32, 256 threads, 8 warps of 64x64 warp tiles.
// NOW 3-STAGE cp.async pipeline (depth-2 prefetch) to hide DRAM latency.
// ---------------------------------------------------------------------------
constexpr int SW   = 20;                    // words per row (16 data + 4 pad)
constexpr int PLWA = 128 * SW;              // 2560 words per A plane
constexpr int PLWB = 256 * SW;              // 5120 words per B plane
constexpr int STAGE_W = 2 * PLWA + 2 * PLWB;        // 15360 words (61440 B)
constexpr int GEMM_SMEM = 3 * STAGE_W * 4;          // 184320 B

template <typename EPI>
__device__ __forceinline__ void gemm_mainloop(
    const __nv_bfloat16* __restrict__ Ah, const __nv_bfloat16* __restrict__ Am,
    const __nv_bfloat16* __restrict__ Bh, const __nv_bfloat16* __restrict__ Bm,
    int m0, int n0, uint32_t* smw, EPI epi)
{
    const uint32_t sbase = (uint32_t)__cvta_generic_to_shared(smw);
    const int tid  = threadIdx.x;
    const int warp = tid >> 5;
    const int lane = tid & 31;
    const int rbase = (warp & 1) * 64;        // 2 m-slabs of 64
    const int cbase = (warp >> 1) * 64;       // 4 n-slabs of 64
    const int lq  = lane >> 2;      // 0..7
    const int lc  = lane & 3;       // 0..3

    float acc[4][8][4];
    #pragma unroll
    for (int i = 0; i < 4; i++)
        #pragma unroll
        for (int j = 0; j < 8; j++)
            #pragma unroll
            for (int r = 0; r < 4; r++) acc[i][j][r] = 0.f;

    auto load_tile = [&](int kt, int st) {
        const int k0 = kt * 32;
        const uint32_t base = sbase + (uint32_t)(st * STAGE_W) * 4u;
        #pragma unroll
        for (int it = 0; it < 2; it++) {
            const int slot = it * 256 + tid;
            const int row = slot >> 2, c4 = slot & 3;
            const uint32_t so = (uint32_t)(row * SW + c4 * 4) * 4u;
            const size_t ga = (size_t)(m0 + row) * 1024 + k0 + c4 * 8;
            cp_async16(base + so, &Ah[ga]);
            cp_async16(base + (uint32_t)(PLWA * 4) + so, &Am[ga]);
        }
        #pragma unroll
        for (int it = 0; it < 4; it++) {
            const int slot = it * 256 + tid;
            const int row = slot >> 2, c4 = slot & 3;
            const uint32_t so = (uint32_t)(row * SW + c4 * 4) * 4u;
            const size_t gb = (size_t)(n0 + row) * 1024 + k0 + c4 * 8;
            cp_async16(base + (uint32_t)(2 * PLWA * 4) + so, &Bh[gb]);
            cp_async16(base + (uint32_t)((2 * PLWA + PLWB) * 4) + so, &Bm[gb]);
        }
    };

    load_tile(0, 0);
    cp_commit();
    load_tile(1, 1);
    cp_commit();

    for (int kt = 0; kt < 32; kt++) {
        // ensure group kt complete: at most 1 newer group (kt+1) pending
        if (kt == 31) cp_wait0(); else cp_wait1();
        __syncthreads();   // also orders compute(kt-1) reads before kt+2 loads
        if (kt + 2 < 32) { load_tile(kt + 2, (kt + 2) % 3); cp_commit(); }

        const uint32_t* AH = smw + (kt % 3) * STAGE_W;
        const uint32_t* AM = AH + PLWA;
        const uint32_t* BH = AH + 2 * PLWA;
        const uint32_t* BM = AH + 2 * PLWA + PLWB;

        #pragma unroll
        for (int ks = 0; ks < 2; ks++) {
            const int kk2 = ks * 8;
            uint32_t ah[4][4], am[4][4];
            #pragma unroll
            for (int mi = 0; mi < 4; mi++) {
                const int rr = rbase + mi * 16 + lq;
                const int o0 = rr * SW + kk2 + lc;
                const int o1 = (rr + 8) * SW + kk2 + lc;
                ah[mi][0] = AH[o0];     am[mi][0] = AM[o0];
                ah[mi][1] = AH[o1];     am[mi][1] = AM[o1];
                ah[mi][2] = AH[o0 + 4]; am[mi][2] = AM[o0 + 4];
                ah[mi][3] = AH[o1 + 4]; am[mi][3] = AM[o1 + 4];
            }
            #pragma unroll
            for (int njp = 0; njp < 2; njp++) {
                uint32_t bh[4][2], bm[4][2];
                #pragma unroll
                for (int j = 0; j < 4; j++) {
                    const int cc = cbase + (njp * 4 + j) * 8 + lq;
                    const int o = cc * SW + kk2 + lc;
                    bh[j][0] = BH[o];     bm[j][0] = BM[o];
                    bh[j][1] = BH[o + 4]; bm[j][1] = BM[o + 4];
                }
                #pragma unroll
                for (int mi = 0; mi < 4; mi++)
                    #pragma unroll
                    for (int j = 0; j < 4; j++) {
                        const int nj = njp * 4 + j;
                        mma_bf16(acc[mi][nj][0], acc[mi][nj][1],
                                 acc[mi][nj][2], acc[mi][nj][3],
                                 am[mi][0], am[mi][1], am[mi][2], am[mi][3],
                                 bh[j][0], bh[j][1]);
                        mma_bf16(acc[mi][nj][0], acc[mi][nj][1],
                                 acc[mi][nj][2], acc[mi][nj][3],
                                 ah[mi][0], ah[mi][1], ah[mi][2], ah[mi][3],
                                 bm[j][0], bm[j][1]);
                        mma_bf16(acc[mi][nj][0], acc[mi][nj][1],
                                 acc[mi][nj][2], acc[mi][nj][3],
                                 ah[mi][0], ah[mi][1], ah[mi][2], ah[mi][3],
                                 bh[j][0], bh[j][1]);
                    }
            }
        }
    }
    __syncthreads();
    epi(acc, rbase, cbase, lq, lc);
}

// Merged Q + KV projection. grid.x = 384 (Q: 128 CTAs, KV: 256 CTAs).
__global__ __launch_bounds__(256, 1) void qkv_gemm_kernel(
    const __nv_bfloat16* __restrict__ Afh, const __nv_bfloat16* __restrict__ Afm,
    const __nv_bfloat16* __restrict__ Ath, const __nv_bfloat16* __restrict__ Atm,
    const __nv_bfloat16* __restrict__ Wqh, const __nv_bfloat16* __restrict__ Wqm,
    const __nv_bfloat16* __restrict__ Wkvh, const __nv_bfloat16* __restrict__ Wkvm,
    const float* __restrict__ bq, const float* __restrict__ bkv,
    __nv_bfloat16* __restrict__ Qh, __nv_bfloat16* __restrict__ Qm,
    __nv_bfloat16* __restrict__ Kh, __nv_bfloat16* __restrict__ Km,
    __nv_bfloat16* __restrict__ Vth, __nv_bfloat16* __restrict__ Vtm)
{
    extern __shared__ uint32_t smw[];
    const int bx = blockIdx.x;

    const __nv_bfloat16 *Ah, *Am, *Bh, *Bm;
    const float* bias;
    int m0, n0, is_v = 0, ncol;
    if (bx < 128) {
        Ah = Afh; Am = Afm; Bh = Wqh; Bm = Wqm; bias = bq;
        m0 = (bx >> 2) * 128; n0 = (bx & 3) * 256; ncol = n0;
    } else {
        const int bxx = bx - 128;
        Ah = Ath; Am = Atm; Bh = Wkvh; Bm = Wkvm; bias = bkv;
        m0 = (bxx >> 3) * 128; n0 = (bxx & 7) * 256;
        if (n0 < 1024) { ncol = n0; }
        else           { ncol = n0 - 1024; is_v = 1; }
    }

    gemm_mainloop(Ah, Am, Bh, Bm, m0, n0, smw,
        [&](float (&acc)[4][8][4], int rbase, int cbase, int lq, int lc) {
            #pragma unroll
            for (int mi = 0; mi < 4; mi++) {
                const int r0 = m0 + rbase + mi * 16 + lq;
                #pragma unroll
                for (int nj = 0; nj < 8; nj++) {
                    const int col = ncol + cbase + nj * 8 + lc * 2;
                    const float b0 = bias[n0 - ncol + col];
                    const float b1 = bias[n0 - ncol + col + 1];
                    float v00 = acc[mi][nj][0] + b0;
                    float v01 = acc[mi][nj][1] + b1;
                    float v10 = acc[mi][nj][2] + b0;
                    float v11 = acc[mi][nj][3] + b1;
                    __nv_bfloat16 h00, h01, h10, h11, q00, q01, q10, q11;
                    bsplit(v00, h00, q00); bsplit(v01, h01, q01);
                    bsplit(v10, h10, q10); bsplit(v11, h11, q11);
                    if (!is_v) {
                        __nv_bfloat16* Dh = (bx < 128) ? Qh : Kh;
                        __nv_bfloat16* Dm = (bx < 128) ? Qm : Km;
                        const size_t o0 = (size_t)r0 * 1024 + col;
                        const size_t o1 = (size_t)(r0 + 8) * 1024 + col;
                        *(uint32_t*)&Dh[o0] = bpack(h00, h01);
                        *(uint32_t*)&Dh[o1] = bpack(h10, h11);
                        *(uint32_t*)&Dm[o0] = bpack(q00, q01);
                        *(uint32_t*)&Dm[o1] = bpack(q10, q11);
                    } else {
                        // V transposed: [b][h][d][s]
                        const int h = col >> 6, d = col & 63;
                        const int bl0 = r0 >> 11, s0 = r0 & 2047;
                        const int bl1 = (r0 + 8) >> 11, s1 = (r0 + 8) & 2047;
                        const size_t i00 = ((size_t)(bl0 * 16 + h) * 64 + d) * 2048 + s0;
                        const size_t i10 = ((size_t)(bl1 * 16 + h) * 64 + d) * 2048 + s1;
                        Vth[i00] = h00;          Vtm[i00] = q00;
                        Vth[i00 + 2048] = h01;   Vtm[i00 + 2048] = q01;
                        Vth[i10] = h10;          Vtm[i10] = q10;
                        Vth[i10 + 2048] = h11;   Vtm[i10 + 2048] = q11;
                    }
                }
            }
        });
}

// Output projection: out = O @ w_out + b_out (fp32 store).
__global__ __launch_bounds__(256, 1) void out_gemm_kernel(
    const __nv_bfloat16* __restrict__ Ah, const __nv_bfloat16* __restrict__ Am,
    const __nv_bfloat16* __restrict__ Bh, const __nv_bfloat16* __restrict__ Bm,
    const float* __restrict__ bias, float* __restrict__ C)
{
    extern __shared__ uint32_t smw[];
    const int m0 = blockIdx.y * 128;
    const int n0 = blockIdx.x * 256;
    gemm_mainloop(Ah, Am, Bh, Bm, m0, n0, smw,
        [&](float (&acc)[4][8][4], int rbase, int cbase, int lq, int lc) {
            #pragma unroll
            for (int mi = 0; mi < 4; mi++) {
                const int r0 = m0 + rbase + mi * 16 + lq;
                #pragma unroll
                for (int nj = 0; nj < 8; nj++) {
                    const int col = n0 + cbase + nj * 8 + lc * 2;
                    const float b0 = bias[col], b1 = bias[col + 1];
                    *(float2*)&C[(size_t)r0 * Fdim + col] =
                        make_float2(acc[mi][nj][0] + b0, acc[mi][nj][1] + b1);
                    *(float2*)&C[(size_t)(r0 + 8) * Fdim + col] =
                        make_float2(acc[mi][nj][2] + b0, acc[mi][nj][3] + b1);
                }
            }
        });
}

// ---------------------------------------------------------------------------
// bf16x3 flash attention — now with 3-stage cp.async pipeline.
// Br=128, Bc=64, d=64. 8 warps, 16 q-rows each. Mask: z >= s -> -1e12f.
// CTA t does 2t+2 kv tiles; row s=0 fixed by row0_kernel.
// ---------------------------------------------------------------------------
constexpr int FST = 36;
constexpr int FTW = 64 * FST;             // 2304 words per plane-stage
constexpr int FLASH_SMEM = 12 * FTW * 4;  // 4 planes x 3 stages = 110592 B

__global__ __launch_bounds__(256) void flash_mma_kernel(
    const __nv_bfloat16* __restrict__ Qh, const __nv_bfloat16* __restrict__ Qm,
    const __nv_bfloat16* __restrict__ Kh, const __nv_bfloat16* __restrict__ Km,
    const __nv_bfloat16* __restrict__ Vth, const __nv_bfloat16* __restrict__ Vtm,
    __nv_bfloat16* __restrict__ Oh, __nv_bfloat16* __restrict__ Om)
{
    extern __shared__ uint32_t smw[];
    const uint32_t sbase = (uint32_t)__cvta_generic_to_shared(smw);

    const int t = 15 - (int)blockIdx.x;
    const int h = blockIdx.y;
    const int b = blockIdx.z;
    const int tid  = threadIdx.x;
    const int warp = tid >> 5;
    const int lane = tid & 31;
    const int lq  = lane >> 2;
    const int lc  = lane & 3;

    auto plane = [&](int p, int st) { return (uint32_t)((p * 3 + st) * FTW); };

    auto load_kv = [&](int kc, int st) {
        #pragma unroll
        for (int it = 0; it < 2; it++) {
            const int slot = it * 256 + tid;
            const int row = slot >> 3;
            const int c8 = slot & 7;
            const uint32_t so = (uint32_t)(row * FST + c8 * 4) * 4u;
            const size_t gk = (size_t)(b * Sseq + kc * 64 + row) * 1024 + h * 64 + c8 * 8;
            cp_async16(sbase + (plane(0, st)) * 4u + so, &Kh[gk]);
            cp_async16(sbase + (plane(1, st)) * 4u + so, &Km[gk]);
            const size_t gv = ((size_t)(b * 16 + h) * 64 + row) * 2048 + kc * 64 + c8 * 8;
            cp_async16(sbase + (plane(2, st)) * 4u + so, &Vth[gv]);
            cp_async16(sbase + (plane(3, st)) * 4u + so, &Vtm[gv]);
        }
    };

    const int nkc = 2 * t + 2;

    load_kv(0, 0);
    cp_commit();
    if (nkc > 1) { load_kv(1, 1); cp_commit(); }

    const uint32_t* Qh32 = (const uint32_t*)Qh;
    const uint32_t* Qm32 = (const uint32_t*)Qm;
    uint32_t qh[4][4], qm[4][4];
    {
        const int qrow = b * Sseq + t * 128 + warp * 16 + lq;
        const size_t qb0 = (size_t)qrow * 512 + h * 32;
        const size_t qb1 = qb0 + 8 * 512;
        #pragma unroll
        for (int ks = 0; ks < 4; ks++) {
            const int o = ks * 8 + lc;
            qh[ks][0] = Qh32[qb0 + o];     qm[ks][0] = Qm32[qb0 + o];
            qh[ks][1] = Qh32[qb1 + o];     qm[ks][1] = Qm32[qb1 + o];
            qh[ks][2] = Qh32[qb0 + o + 4]; qm[ks][2] = Qm32[qb0 + o + 4];
            qh[ks][3] = Qh32[qb1 + o + 4]; qm[ks][3] = Qm32[qb1 + o + 4];
        }
    }

    float oacc[8][4];
    #pragma unroll
    for (int nt = 0; nt < 8; nt++)
        #pragma unroll
        for (int r = 0; r < 4; r++) oacc[nt][r] = 0.f;
    float m0 = -3.0e38f, m1 = -3.0e38f, l0 = 0.f, l1 = 0.f;

    const int row0 = t * 128 + warp * 16 + lq;
    const int row1 = row0 + 8;

    for (int kc = 0; kc < nkc; kc++) {
        if (kc + 1 < nkc) cp_wait1(); else cp_wait0();
        __syncthreads();
        if (kc + 2 < nkc) { load_kv(kc + 2, (kc + 2) % 3); cp_commit(); }

        const int st = kc % 3;
        const uint32_t* KH = smw + plane(0, st);
        const uint32_t* KM = smw + plane(1, st);
        const uint32_t* VH = smw + plane(2, st);
        const uint32_t* VM = smw + plane(3, st);

        float sacc[8][4];
        #pragma unroll
        for (int nt = 0; nt < 8; nt++)
            #pragma unroll
            for (int r = 0; r < 4; r++) sacc[nt][r] = 0.f;

        #pragma unroll
        for (int ks = 0; ks < 4; ks++) {
            #pragma unroll
            for (int nt = 0; nt < 8; nt++) {
                const int ko = (nt * 8 + lq) * FST + ks * 8 + lc;
                const uint32_t bh0 = KH[ko], bh1 = KH[ko + 4];
                const uint32_t bm0 = KM[ko], bm1 = KM[ko + 4];
                mma_bf16(sacc[nt][0], sacc[nt][1], sacc[nt][2], sacc[nt][3],
                         qm[ks][0], qm[ks][1], qm[ks][2], qm[ks][3], bh0, bh1);
                mma_bf16(sacc[nt][0], sacc[nt][1], sacc[nt][2], sacc[nt][3],
                         qh[ks][0], qh[ks][1], qh[ks][2], qh[ks][3], bm0, bm1);
                mma_bf16(sacc[nt][0], sacc[nt][1], sacc[nt][2], sacc[nt][3],
                         qh[ks][0], qh[ks][1], qh[ks][2], qh[ks][3], bh0, bh1);
            }
        }

        #pragma unroll
        for (int nt = 0; nt < 8; nt++) {
            const int cb = kc * 64 + nt * 8 + 2 * lc;
            if (cb     >= row0) sacc[nt][0] = -1.0e12f;
            if (cb + 1 >= row0) sacc[nt][1] = -1.0e12f;
            if (cb     >= row1) sacc[nt][2] = -1.0e12f;
            if (cb + 1 >= row1) sacc[nt][3] = -1.0e12f;
        }

        float mt0 = -3.0e38f, mt1 = -3.0e38f;
        #pragma unroll
        for (int nt = 0; nt < 8; nt++) {
            mt0 = fmaxf(mt0, fmaxf(sacc[nt][0], sacc[nt][1]));
            mt1 = fmaxf(mt1, fmaxf(sacc[nt][2], sacc[nt][3]));
        }
        mt0 = fmaxf(mt0, __shfl_xor_sync(0xffffffffu, mt0, 1));
        mt0 = fmaxf(mt0, __shfl_xor_sync(0xffffffffu, mt0, 2));
        mt1 = fmaxf(mt1, __shfl_xor_sync(0xffffffffu, mt1, 1));
        mt1 = fmaxf(mt1, __shfl_xor_sync(0xffffffffu, mt1, 2));
        const float mn0 = fmaxf(m0, mt0);
        const float mn1 = fmaxf(m1, mt1);
        const float sc0 = __expf(m0 - mn0);
        const float sc1 = __expf(m1 - mn1);
        float ls0 = 0.f, ls1 = 0.f;
        #pragma unroll
        for (int nt = 0; nt < 8; nt++) {
            sacc[nt][0] = __expf(sacc[nt][0] - mn0);
            sacc[nt][1] = __expf(sacc[nt][1] - mn0);
            sacc[nt][2] = __expf(sacc[nt][2] - mn1);
            sacc[nt][3] = __expf(sacc[nt][3] - mn1);
            ls0 += sacc[nt][0] + sacc[nt][1];
            ls1 += sacc[nt][2] + sacc[nt][3];
        }
        l0 = l0 * sc0 + ls0;
        l1 = l1 * sc1 + ls1;
        m0 = mn0; m1 = mn1;
        #pragma unroll
        for (int nt = 0; nt < 8; nt++) {
            oacc[nt][0] *= sc0; oacc[nt][1] *= sc0;
            oacc[nt][2] *= sc1; oacc[nt][3] *= sc1;
        }

        #pragma unroll
        for (int ks = 0; ks < 4; ks++) {
            __nv_bfloat16 h0, h1, h2, h3, h4, h5, h6, h7;
            __nv_bfloat16 w0, w1, w2, w3, w4, w5, w6, w7;
            bsplit(sacc[2 * ks][0], h0, w0); bsplit(sacc[2 * ks][1], h1, w1);
            bsplit(sacc[2 * ks][2], h2, w2); bsplit(sacc[2 * ks][3], h3, w3);
            bsplit(sacc[2 * ks + 1][0], h4, w4); bsplit(sacc[2 * ks + 1][1], h5, w5);
            bsplit(sacc[2 * ks + 1][2], h6, w6); bsplit(sacc[2 * ks + 1][3], h7, w7);
            const uint32_t pah0 = bpack(h0, h1), pah1 = bpack(h2, h3);
            const uint32_t pah2 = bpack(h4, h5), pah3 = bpack(h6, h7);
            const uint32_t pam0 = bpack(w0, w1), pam1 = bpack(w2, w3);
            const uint32_t pam2 = bpack(w4, w5), pam3 = bpack(w6, w7);
            #pragma unroll
            for (int nt = 0; nt < 8; nt++) {
                const int vo = (nt * 8 + lq) * FST + ks * 8 + lc;
                const uint32_t vh0 = VH[vo], vh1 = VH[vo + 4];
                const uint32_t vm0 = VM[vo], vm1 = VM[vo + 4];
                mma_bf16(oacc[nt][0], oacc[nt][1], oacc[nt][2], oacc[nt][3],
                         pam0, pam1, pam2, pam3, vh0, vh1);
                mma_bf16(oacc[nt][0], oacc[nt][1], oacc[nt][2], oacc[nt][3],
                         pah0, pah1, pah2, pah3, vm0, vm1);
                mma_bf16(oacc[nt][0], oacc[nt][1], oacc[nt][2], oacc[nt][3],
                         pah0, pah1, pah2, pah3, vh0, vh1);
            }
        }
    }

    l0 += __shfl_xor_sync(0xffffffffu, l0, 1);
    l0 += __shfl_xor_sync(0xffffffffu, l0, 2);
    l1 += __shfl_xor_sync(0xffffffffu, l1, 1);
    l1 += __shfl_xor_sync(0xffffffffu, l1, 2);
    const float inv0 = 1.f / l0;
    const float inv1 = 1.f / l1;

    const size_t ob = ((size_t)(b * Sseq + t * 128 + warp * 16 + lq)) * 1024 + h * 64;
    #pragma unroll
    for (int nt = 0; nt < 8; nt++) {
        const int cb = nt * 8 + 2 * lc;
        float v00 = oacc[nt][0] * inv0, v01 = oacc[nt][1] * inv0;
        float v10 = oacc[nt][2] * inv1, v11 = oacc[nt][3] * inv1;
        __nv_bfloat16 h00, h01, h10, h11, m00, m01, m10, m11;
        bsplit(v00, h00, m00); bsplit(v01, h01, m01);
        bsplit(v10, h10, m10); bsplit(v11, h11, m11);
        *(uint32_t*)&Oh[ob + cb] = bpack(h00, h01);
        *(uint32_t*)&Oh[ob + 8 * 1024 + cb] = bpack(h10, h11);
        *(uint32_t*)&Om[ob + cb] = bpack(m00, m01);
        *(uint32_t*)&Om[ob + 8 * 1024 + cb] = bpack(m10, m11);
    }
}

// ---------------------------------------------------------------------------
extern "C" void kernel_launch(void* const* d_in, const int* in_sizes, int n_in,
                              void* d_out, int out_size)
{
    (void)in_sizes; (void)n_in; (void)out_size;
    const float* attend_from = (const float*)d_in[0];
    const float* attend_to   = (const float*)d_in[1];
    const float* w_q   = (const float*)d_in[2];
    const float* b_q   = (const float*)d_in[3];
    const float* w_kv  = (const float*)d_in[4];
    const float* b_kv  = (const float*)d_in[5];
    const float* w_out = (const float*)d_in[6];
    const float* b_out = (const float*)d_in[7];
    float* out = (float*)d_out;

    __nv_bfloat16 *afh, *afm, *ath, *atm, *wqh, *wqm, *wkvh, *wkvm, *woh, *wom;
    __nv_bfloat16 *qh, *qm, *kh, *km, *vth, *vtm, *oh, *om;
    cudaGetSymbolAddress((void**)&afh, g_Afh);
    cudaGetSymbolAddress((void**)&afm, g_Afm);
    cudaGetSymbolAddress((void**)&ath, g_Ath);
    cudaGetSymbolAddress((void**)&atm, g_Atm);
    cudaGetSymbolAddress((void**)&wqh, g_Wqh);
    cudaGetSymbolAddress((void**)&wqm, g_Wqm);
    cudaGetSymbolAddress((void**)&wkvh, g_Wkvh);
    cudaGetSymbolAddress((void**)&wkvm, g_Wkvm);
    cudaGetSymbolAddress((void**)&woh, g_Woh);
    cudaGetSymbolAddress((void**)&wom, g_Wom);
    cudaGetSymbolAddress((void**)&qh, g_Qh);
    cudaGetSymbolAddress((void**)&qm, g_Qm);
    cudaGetSymbolAddress((void**)&kh, g_Kh);
    cudaGetSymbolAddress((void**)&km, g_Km);
    cudaGetSymbolAddress((void**)&vth, g_Vth);
    cudaGetSymbolAddress((void**)&vtm, g_Vtm);
    cudaGetSymbolAddress((void**)&oh, g_Oh);
    cudaGetSymbolAddress((void**)&om, g_Om);

    cudaFuncSetAttribute(qkv_gemm_kernel,
                         cudaFuncAttributeMaxDynamicSharedMemorySize, GEMM_SMEM);
    cudaFuncSetAttribute(out_gemm_kernel,
                         cudaFuncAttributeMaxDynamicSharedMemorySize, GEMM_SMEM);
    cudaFuncSetAttribute(flash_mma_kernel,
                         cudaFuncAttributeMaxDynamicSharedMemorySize, FLASH_SMEM);

    // 0) pre-split activations, split+transpose weights
    {
        const int nA = Mrows * Fdim / 4;
        asplit_kernel<<<(nA + 255) / 256, 256>>>(attend_from, afh, afm, nA);
        asplit_kernel<<<(nA + 255) / 256, 256>>>(attend_to,   ath, atm, nA);
        wsplit_kernel<<<dim3(32, 32), 256>>>(w_q,   wqh,  wqm,  1024, 1024);
        wsplit_kernel<<<dim3(32, 64), 256>>>(w_kv,  wkvh, wkvm, 1024, 2048);
        wsplit_kernel<<<dim3(32, 32), 256>>>(w_out, woh,  wom,  1024, 1024);
    }

    // 1) merged Q + KV projection (128 Q CTAs + 256 KV CTAs)
    qkv_gemm_kernel<<<384, 256, GEMM_SMEM>>>(
        afh, afm, ath, atm, wqh, wqm, wkvh, wkvm, b_q, b_kv,
        qh, qm, kh, km, vth, vtm);

    // 2) flash attention (row s=0 via row0_kernel)
    {
        dim3 grid(Sseq / 128, Hh, Bsz);
        flash_mma_kernel<<<grid, 256, FLASH_SMEM>>>(
            qh, qm, kh, km, vth, vtm, oh, om);
    }

    // 2b) exact fix-up for fully-masked row s=0
    {
        dim3 grid(1024, Bsz);
        row0_kernel<<<grid, 256>>>(vth, vtm, oh, om);
    }

    // 3) output projection
    {
        dim3 grid(Fdim / 256, Mrows / 128);
        out_gemm_kernel<<<grid, 256, GEMM_SMEM>>>(oh, om, woh, wom, b_out, out);
    }
}

// round 14
// speedup vs baseline: 1.1886x; 1.1886x over previous
#include <cuda_runtime.h>
#include <cuda_fp16.h>
#include <math.h>
#include <stdint.h>

// Problem constants (fixed shapes)
constexpr int Bsz  = 2;
constexpr int Sseq = 2048;
constexpr int Fdim = 1024;
constexpr int Hh   = 16;
constexpr int Dh   = 64;
constexpr int Mrows = Bsz * Sseq;   // 4096

// Scratch (device globals, allocation-free). Operands live as fp16 planes:
// hi = fp16(x), mid = fp16(x - hi); hi+mid recovers fp32 to ~2^-22.
__device__ __half g_Afh[(size_t)Mrows * Fdim];
__device__ __half g_Afm[(size_t)Mrows * Fdim];
__device__ __half g_Ath[(size_t)Mrows * Fdim];
__device__ __half g_Atm[(size_t)Mrows * Fdim];
__device__ __half g_Wqh[(size_t)Fdim * Fdim];      // w_q^T  [n][k]
__device__ __half g_Wqm[(size_t)Fdim * Fdim];
__device__ __half g_Wkvh[(size_t)2 * Fdim * Fdim]; // w_kv^T [n][k]
__device__ __half g_Wkvm[(size_t)2 * Fdim * Fdim];
__device__ __half g_Woh[(size_t)Fdim * Fdim];      // w_out^T [n][k] (hi only used)
__device__ __half g_Wom[(size_t)Fdim * Fdim];
__device__ __half g_Qh[(size_t)Mrows * Fdim];
__device__ __half g_Qm[(size_t)Mrows * Fdim];
__device__ __half g_Kh[(size_t)Mrows * Fdim];
__device__ __half g_Km[(size_t)Mrows * Fdim];
__device__ __half g_Vth[(size_t)Mrows * Fdim];     // V^T [b][h][d][s]
__device__ __half g_Vtm[(size_t)Mrows * Fdim];
__device__ __half g_Oh[(size_t)Mrows * Fdim];
__device__ __half g_Om[(size_t)Mrows * Fdim];

// ---------------------------------------------------------------------------
// PTX helpers
// ---------------------------------------------------------------------------
__device__ __forceinline__ void cp_async16(uint32_t saddr, const void* gptr) {
    asm volatile("cp.async.cg.shared.global [%0], [%1], 16;"
                 :: "r"(saddr), "l"(gptr));
}
__device__ __forceinline__ void cp_commit() {
    asm volatile("cp.async.commit_group;");
}
__device__ __forceinline__ void cp_wait0() {
    asm volatile("cp.async.wait_group 0;");
}

__device__ __forceinline__ void mma_f16(
    float& d0, float& d1, float& d2, float& d3,
    uint32_t a0, uint32_t a1, uint32_t a2, uint32_t a3,
    uint32_t b0, uint32_t b1)
{
    asm volatile(
        "mma.sync.aligned.m16n8k16.row.col.f32.f16.f16.f32 "
        "{%0,%1,%2,%3},{%4,%5,%6,%7},{%8,%9},{%0,%1,%2,%3};"
        : "+f"(d0), "+f"(d1), "+f"(d2), "+f"(d3)
        : "r"(a0), "r"(a1), "r"(a2), "r"(a3), "r"(b0), "r"(b1));
}

__device__ __forceinline__ void hsplit(float v, __half& h, __half& m) {
    h = __float2half_rn(v);
    m = __float2half_rn(v - __half2float(h));
}
__device__ __forceinline__ uint32_t hpack(__half lo, __half hi) {
    __half2 t;
    t.x = lo; t.y = hi;
    return *reinterpret_cast<uint32_t*>(&t);
}

// ---------------------------------------------------------------------------
// Pre-pass: elementwise split (no transpose) for activations [M][K].
// ---------------------------------------------------------------------------
__global__ __launch_bounds__(256) void asplit_kernel(
    const float* __restrict__ src, __half* __restrict__ hi,
    __half* __restrict__ mid, int n4)
{
    const int i = blockIdx.x * 256 + threadIdx.x;
    if (i >= n4) return;
    float4 v = ((const float4*)src)[i];
    __half h0, h1, h2, h3, m0, m1, m2, m3;
    hsplit(v.x, h0, m0); hsplit(v.y, h1, m1);
    hsplit(v.z, h2, m2); hsplit(v.w, h3, m3);
    ((uint2*)hi)[i]  = make_uint2(hpack(h0, h1), hpack(h2, h3));
    ((uint2*)mid)[i] = make_uint2(hpack(m0, m1), hpack(m2, m3));
}

// Pre-pass: split + transpose weights w[k][n] -> planes [n][k].
__global__ __launch_bounds__(256) void wsplit_kernel(
    const float* __restrict__ w, __half* __restrict__ th,
    __half* __restrict__ tm, int K, int N)
{
    __shared__ float ts[32][33];
    const int k0 = blockIdx.x * 32;
    const int n0 = blockIdx.y * 32;
    const int tx = threadIdx.x & 31;
    const int ty = threadIdx.x >> 5;
    #pragma unroll
    for (int i = 0; i < 4; i++)
        ts[ty + 8 * i][tx] = w[(size_t)(k0 + ty + 8 * i) * N + n0 + tx];
    __syncthreads();
    #pragma unroll
    for (int i = 0; i < 4; i++) {
        float v = ts[tx][ty + 8 * i];
        __half h, m;
        hsplit(v, h, m);
        const size_t o = (size_t)(n0 + ty + 8 * i) * K + k0 + tx;
        th[o] = h;
        tm[o] = m;
    }
}

// Row-0 fix: fully-masked row -> uniform softmax -> mean of V rows.
__global__ __launch_bounds__(256) void row0_kernel(
    const __half* __restrict__ Vth, const __half* __restrict__ Vtm,
    __half* __restrict__ Oh, __half* __restrict__ Om)
{
    __shared__ float red[256];
    const int f = blockIdx.x;
    const int b = blockIdx.y;
    const int h = f >> 6, d = f & 63;
    const size_t base = ((size_t)(b * 16 + h) * 64 + d) * 2048;
    float s = 0.f;
    for (int i = threadIdx.x; i < 2048; i += 256)
        s += __half2float(Vth[base + i]) + __half2float(Vtm[base + i]);
    red[threadIdx.x] = s;
    __syncthreads();
    for (int o = 128; o > 0; o >>= 1) {
        if (threadIdx.x < o) red[threadIdx.x] += red[threadIdx.x + o];
        __syncthreads();
    }
    if (threadIdx.x == 0) {
        const float v = red[0] * (1.f / 2048.f);
        __half hh, mm;
        hsplit(v, hh, mm);
        const size_t o = (size_t)(b * Sseq) * 1024 + f;
        Oh[o] = hh;
        Om[o] = mm;
    }
}

// ---------------------------------------------------------------------------
// fp16 GEMM core: C[M,N] = A[M,1024] @ W^T[n][k] (+bias via epilogue).
// CTA tile 128x256, BK=32, 256 threads, 8 warps of 64x64 warp tiles,
// 2-stage cp.async pipeline (R12 structure).
// use_bm=true : 3 MMAs (Am·Bh + Ah·Bm + Ah·Bh), err ~2^-22.
// use_bm=false: 2 MMAs (Am·Bh + Ah·Bh), B-mid never loaded, err ~2.8e-4.
// ---------------------------------------------------------------------------
constexpr int SW   = 20;                    // words per row (16 data + 4 pad)
constexpr int PLWA = 128 * SW;              // 2560 words per A plane
constexpr int PLWB = 256 * SW;              // 5120 words per B plane
constexpr int STAGE_W = 2 * PLWA + 2 * PLWB;        // 15360 words
constexpr int GEMM_SMEM = 2 * STAGE_W * 4;          // 122880 B

template <typename EPI>
__device__ __forceinline__ void gemm_mainloop(
    const __half* __restrict__ Ah, const __half* __restrict__ Am,
    const __half* __restrict__ Bh, const __half* __restrict__ Bm,
    int m0, int n0, bool use_bm, uint32_t* smw, EPI epi)
{
    const uint32_t sbase = (uint32_t)__cvta_generic_to_shared(smw);
    const int tid  = threadIdx.x;
    const int warp = tid >> 5;
    const int lane = tid & 31;
    const int rbase = (warp & 1) * 64;        // 2 m-slabs of 64
    const int cbase = (warp >> 1) * 64;       // 4 n-slabs of 64
    const int lq  = lane >> 2;      // 0..7
    const int lc  = lane & 3;       // 0..3

    float acc[4][8][4];
    #pragma unroll
    for (int i = 0; i < 4; i++)
        #pragma unroll
        for (int j = 0; j < 8; j++)
            #pragma unroll
            for (int r = 0; r < 4; r++) acc[i][j][r] = 0.f;

    auto load_tile = [&](int kt, int st) {
        const int k0 = kt * 32;
        const uint32_t base = sbase + (uint32_t)(st * STAGE_W) * 4u;
        #pragma unroll
        for (int it = 0; it < 2; it++) {
            const int slot = it * 256 + tid;
            const int row = slot >> 2, c4 = slot & 3;
            const uint32_t so = (uint32_t)(row * SW + c4 * 4) * 4u;
            const size_t ga = (size_t)(m0 + row) * 1024 + k0 + c4 * 8;
            cp_async16(base + so, &Ah[ga]);
            cp_async16(base + (uint32_t)(PLWA * 4) + so, &Am[ga]);
        }
        #pragma unroll
        for (int it = 0; it < 4; it++) {
            const int slot = it * 256 + tid;
            const int row = slot >> 2, c4 = slot & 3;
            const uint32_t so = (uint32_t)(row * SW + c4 * 4) * 4u;
            const size_t gb = (size_t)(n0 + row) * 1024 + k0 + c4 * 8;
            cp_async16(base + (uint32_t)(2 * PLWA * 4) + so, &Bh[gb]);
            if (use_bm)
                cp_async16(base + (uint32_t)((2 * PLWA + PLWB) * 4) + so, &Bm[gb]);
        }
    };

    load_tile(0, 0);
    cp_commit();

    for (int kt = 0; kt < 32; kt++) {
        cp_wait0();
        __syncthreads();   // also orders compute(kt-1) before loads(kt+1)
        if (kt + 1 < 32) { load_tile(kt + 1, (kt + 1) & 1); cp_commit(); }

        const uint32_t* AH = smw + (kt & 1) * STAGE_W;
        const uint32_t* AM = AH + PLWA;
        const uint32_t* BH = AH + 2 * PLWA;
        const uint32_t* BM = AH + 2 * PLWA + PLWB;

        #pragma unroll
        for (int ks = 0; ks < 2; ks++) {
            const int kk2 = ks * 8;
            uint32_t ah[4][4], am[4][4];
            #pragma unroll
            for (int mi = 0; mi < 4; mi++) {
                const int rr = rbase + mi * 16 + lq;
                const int o0 = rr * SW + kk2 + lc;
                const int o1 = (rr + 8) * SW + kk2 + lc;
                ah[mi][0] = AH[o0];     am[mi][0] = AM[o0];
                ah[mi][1] = AH[o1];     am[mi][1] = AM[o1];
                ah[mi][2] = AH[o0 + 4]; am[mi][2] = AM[o0 + 4];
                ah[mi][3] = AH[o1 + 4]; am[mi][3] = AM[o1 + 4];
            }
            #pragma unroll
            for (int njp = 0; njp < 2; njp++) {
                uint32_t bh[4][2], bm[4][2];
                #pragma unroll
                for (int j = 0; j < 4; j++) {
                    const int cc = cbase + (njp * 4 + j) * 8 + lq;
                    const int o = cc * SW + kk2 + lc;
                    bh[j][0] = BH[o];
                    bh[j][1] = BH[o + 4];
                    if (use_bm) { bm[j][0] = BM[o]; bm[j][1] = BM[o + 4]; }
                }
                #pragma unroll
                for (int mi = 0; mi < 4; mi++)
                    #pragma unroll
                    for (int j = 0; j < 4; j++) {
                        const int nj = njp * 4 + j;
                        mma_f16(acc[mi][nj][0], acc[mi][nj][1],
                                acc[mi][nj][2], acc[mi][nj][3],
                                am[mi][0], am[mi][1], am[mi][2], am[mi][3],
                                bh[j][0], bh[j][1]);
                        if (use_bm)
                            mma_f16(acc[mi][nj][0], acc[mi][nj][1],
                                    acc[mi][nj][2], acc[mi][nj][3],
                                    ah[mi][0], ah[mi][1], ah[mi][2], ah[mi][3],
                                    bm[j][0], bm[j][1]);
                        mma_f16(acc[mi][nj][0], acc[mi][nj][1],
                                acc[mi][nj][2], acc[mi][nj][3],
                                ah[mi][0], ah[mi][1], ah[mi][2], ah[mi][3],
                                bh[j][0], bh[j][1]);
                    }
            }
        }
    }
    __syncthreads();
    epi(acc, rbase, cbase, lq, lc);
}

// Merged Q + KV projection. grid.x = 384 (Q: 128 CTAs, KV: 256 CTAs).
// Q/K tiles: 3-MMA (logit path, error-sensitive). V tiles: 2-MMA.
__global__ __launch_bounds__(256, 1) void qkv_gemm_kernel(
    const __half* __restrict__ Afh, const __half* __restrict__ Afm,
    const __half* __restrict__ Ath, const __half* __restrict__ Atm,
    const __half* __restrict__ Wqh, const __half* __restrict__ Wqm,
    const __half* __restrict__ Wkvh, const __half* __restrict__ Wkvm,
    const float* __restrict__ bq, const float* __restrict__ bkv,
    __half* __restrict__ Qh, __half* __restrict__ Qm,
    __half* __restrict__ Kh, __half* __restrict__ Km,
    __half* __restrict__ Vth, __half* __restrict__ Vtm)
{
    extern __shared__ uint32_t smw[];
    const int bx = blockIdx.x;

    const __half *Ah, *Am, *Bh, *Bm;
    const float* bias;
    int m0, n0, is_v = 0, ncol;
    if (bx < 128) {
        Ah = Afh; Am = Afm; Bh = Wqh; Bm = Wqm; bias = bq;
        m0 = (bx >> 2) * 128; n0 = (bx & 3) * 256; ncol = n0;
    } else {
        const int bxx = bx - 128;
        Ah = Ath; Am = Atm; Bh = Wkvh; Bm = Wkvm; bias = bkv;
        m0 = (bxx >> 3) * 128; n0 = (bxx & 7) * 256;
        if (n0 < 1024) { ncol = n0; }
        else           { ncol = n0 - 1024; is_v = 1; }
    }

    gemm_mainloop(Ah, Am, Bh, Bm, m0, n0, /*use_bm=*/!is_v, smw,
        [&](float (&acc)[4][8][4], int rbase, int cbase, int lq, int lc) {
            #pragma unroll
            for (int mi = 0; mi < 4; mi++) {
                const int r0 = m0 + rbase + mi * 16 + lq;
                #pragma unroll
                for (int nj = 0; nj < 8; nj++) {
                    const int col = ncol + cbase + nj * 8 + lc * 2;
                    const float b0 = bias[n0 - ncol + col];
                    const float b1 = bias[n0 - ncol + col + 1];
                    float v00 = acc[mi][nj][0] + b0;
                    float v01 = acc[mi][nj][1] + b1;
                    float v10 = acc[mi][nj][2] + b0;
                    float v11 = acc[mi][nj][3] + b1;
                    __half h00, h01, h10, h11, q00, q01, q10, q11;
                    hsplit(v00, h00, q00); hsplit(v01, h01, q01);
                    hsplit(v10, h10, q10); hsplit(v11, h11, q11);
                    if (!is_v) {
                        __half* Dh = (bx < 128) ? Qh : Kh;
                        __half* Dm = (bx < 128) ? Qm : Km;
                        const size_t o0 = (size_t)r0 * 1024 + col;
                        const size_t o1 = (size_t)(r0 + 8) * 1024 + col;
                        *(uint32_t*)&Dh[o0] = hpack(h00, h01);
                        *(uint32_t*)&Dh[o1] = hpack(h10, h11);
                        *(uint32_t*)&Dm[o0] = hpack(q00, q01);
                        *(uint32_t*)&Dm[o1] = hpack(q10, q11);
                    } else {
                        // V transposed: [b][h][d][s]
                        const int h = col >> 6, d = col & 63;
                        const int bl0 = r0 >> 11, s0 = r0 & 2047;
                        const int bl1 = (r0 + 8) >> 11, s1 = (r0 + 8) & 2047;
                        const size_t i00 = ((size_t)(bl0 * 16 + h) * 64 + d) * 2048 + s0;
                        const size_t i10 = ((size_t)(bl1 * 16 + h) * 64 + d) * 2048 + s1;
                        Vth[i00] = h00;          Vtm[i00] = q00;
                        Vth[i00 + 2048] = h01;   Vtm[i00 + 2048] = q01;
                        Vth[i10] = h10;          Vtm[i10] = q10;
                        Vth[i10 + 2048] = h11;   Vtm[i10 + 2048] = q11;
                    }
                }
            }
        });
}

// Output projection: out = O @ w_out + b_out (fp32 store). 2-MMA path.
__global__ __launch_bounds__(256, 1) void out_gemm_kernel(
    const __half* __restrict__ Ah, const __half* __restrict__ Am,
    const __half* __restrict__ Bh, const __half* __restrict__ Bm,
    const float* __restrict__ bias, float* __restrict__ C)
{
    extern __shared__ uint32_t smw[];
    const int m0 = blockIdx.y * 128;
    const int n0 = blockIdx.x * 256;
    gemm_mainloop(Ah, Am, Bh, Bm, m0, n0, /*use_bm=*/false, smw,
        [&](float (&acc)[4][8][4], int rbase, int cbase, int lq, int lc) {
            #pragma unroll
            for (int mi = 0; mi < 4; mi++) {
                const int r0 = m0 + rbase + mi * 16 + lq;
                #pragma unroll
                for (int nj = 0; nj < 8; nj++) {
                    const int col = n0 + cbase + nj * 8 + lc * 2;
                    const float b0 = bias[col], b1 = bias[col + 1];
                    *(float2*)&C[(size_t)r0 * Fdim + col] =
                        make_float2(acc[mi][nj][0] + b0, acc[mi][nj][1] + b1);
                    *(float2*)&C[(size_t)(r0 + 8) * Fdim + col] =
                        make_float2(acc[mi][nj][2] + b0, acc[mi][nj][3] + b1);
                }
            }
        });
}

// ---------------------------------------------------------------------------
// fp16 flash attention. Br=128, Bc=64, d=64. 8 warps, 16 q-rows each.
// S: 3 MMAs (Q hi/mid x K hi/mid, logit-accurate). O: 2 MMAs
// (P hi-only fp16 x V hi+mid). Mask: z >= s -> -1e12f. CTA t: 2t+2 tiles.
// ---------------------------------------------------------------------------
constexpr int FST = 36;
constexpr int FTW = 64 * FST;
constexpr int FLASH_SMEM = 8 * FTW * 4;   // 4 planes x 2 stages = 73728 B

__global__ __launch_bounds__(256) void flash_mma_kernel(
    const __half* __restrict__ Qh, const __half* __restrict__ Qm,
    const __half* __restrict__ Kh, const __half* __restrict__ Km,
    const __half* __restrict__ Vth, const __half* __restrict__ Vtm,
    __half* __restrict__ Oh, __half* __restrict__ Om)
{
    extern __shared__ uint32_t smw[];
    const uint32_t sbase = (uint32_t)__cvta_generic_to_shared(smw);

    const int t = 15 - (int)blockIdx.x;
    const int h = blockIdx.y;
    const int b = blockIdx.z;
    const int tid  = threadIdx.x;
    const int warp = tid >> 5;
    const int lane = tid & 31;
    const int lq  = lane >> 2;
    const int lc  = lane & 3;

    auto plane = [&](int p, int st) { return (uint32_t)((p * 2 + st) * FTW); };

    auto load_kv = [&](int kc, int st) {
        #pragma unroll
        for (int it = 0; it < 2; it++) {
            const int slot = it * 256 + tid;
            const int row = slot >> 3;
            const int c8 = slot & 7;
            const uint32_t so = (uint32_t)(row * FST + c8 * 4) * 4u;
            const size_t gk = (size_t)(b * Sseq + kc * 64 + row) * 1024 + h * 64 + c8 * 8;
            cp_async16(sbase + (plane(0, st)) * 4u + so, &Kh[gk]);
            cp_async16(sbase + (plane(1, st)) * 4u + so, &Km[gk]);
            const size_t gv = ((size_t)(b * 16 + h) * 64 + row) * 2048 + kc * 64 + c8 * 8;
            cp_async16(sbase + (plane(2, st)) * 4u + so, &Vth[gv]);
            cp_async16(sbase + (plane(3, st)) * 4u + so, &Vtm[gv]);
        }
    };

    load_kv(0, 0);
    cp_commit();

    const uint32_t* Qh32 = (const uint32_t*)Qh;
    const uint32_t* Qm32 = (const uint32_t*)Qm;
    uint32_t qh[4][4], qm[4][4];
    {
        const int qrow = b * Sseq + t * 128 + warp * 16 + lq;
        const size_t qb0 = (size_t)qrow * 512 + h * 32;
        const size_t qb1 = qb0 + 8 * 512;
        #pragma unroll
        for (int ks = 0; ks < 4; ks++) {
            const int o = ks * 8 + lc;
            qh[ks][0] = Qh32[qb0 + o];     qm[ks][0] = Qm32[qb0 + o];
            qh[ks][1] = Qh32[qb1 + o];     qm[ks][1] = Qm32[qb1 + o];
            qh[ks][2] = Qh32[qb0 + o + 4]; qm[ks][2] = Qm32[qb0 + o + 4];
            qh[ks][3] = Qh32[qb1 + o + 4]; qm[ks][3] = Qm32[qb1 + o + 4];
        }
    }

    float oacc[8][4];
    #pragma unroll
    for (int nt = 0; nt < 8; nt++)
        #pragma unroll
        for (int r = 0; r < 4; r++) oacc[nt][r] = 0.f;
    float m0 = -3.0e38f, m1 = -3.0e38f, l0 = 0.f, l1 = 0.f;

    const int row0 = t * 128 + warp * 16 + lq;
    const int row1 = row0 + 8;
    const int nkc = 2 * t + 2;

    for (int kc = 0; kc < nkc; kc++) {
        cp_wait0();
        __syncthreads();
        if (kc + 1 < nkc) { load_kv(kc + 1, (kc + 1) & 1); cp_commit(); }

        const int st = kc & 1;
        const uint32_t* KH = smw + plane(0, st);
        const uint32_t* KM = smw + plane(1, st);
        const uint32_t* VH = smw + plane(2, st);
        const uint32_t* VM = smw + plane(3, st);

        float sacc[8][4];
        #pragma unroll
        for (int nt = 0; nt < 8; nt++)
            #pragma unroll
            for (int r = 0; r < 4; r++) sacc[nt][r] = 0.f;

        #pragma unroll
        for (int ks = 0; ks < 4; ks++) {
            #pragma unroll
            for (int nt = 0; nt < 8; nt++) {
                const int ko = (nt * 8 + lq) * FST + ks * 8 + lc;
                const uint32_t bh0 = KH[ko], bh1 = KH[ko + 4];
                const uint32_t bm0 = KM[ko], bm1 = KM[ko + 4];
                mma_f16(sacc[nt][0], sacc[nt][1], sacc[nt][2], sacc[nt][3],
                        qm[ks][0], qm[ks][1], qm[ks][2], qm[ks][3], bh0, bh1);
                mma_f16(sacc[nt][0], sacc[nt][1], sacc[nt][2], sacc[nt][3],
                        qh[ks][0], qh[ks][1], qh[ks][2], qh[ks][3], bm0, bm1);
                mma_f16(sacc[nt][0], sacc[nt][1], sacc[nt][2], sacc[nt][3],
                        qh[ks][0], qh[ks][1], qh[ks][2], qh[ks][3], bh0, bh1);
            }
        }

        #pragma unroll
        for (int nt = 0; nt < 8; nt++) {
            const int cb = kc * 64 + nt * 8 + 2 * lc;
            if (cb     >= row0) sacc[nt][0] = -1.0e12f;
            if (cb + 1 >= row0) sacc[nt][1] = -1.0e12f;
            if (cb     >= row1) sacc[nt][2] = -1.0e12f;
            if (cb + 1 >= row1) sacc[nt][3] = -1.0e12f;
        }

        float mt0 = -3.0e38f, mt1 = -3.0e38f;
        #pragma unroll
        for (int nt = 0; nt < 8; nt++) {
            mt0 = fmaxf(mt0, fmaxf(sacc[nt][0], sacc[nt][1]));
            mt1 = fmaxf(mt1, fmaxf(sacc[nt][2], sacc[nt][3]));
        }
        mt0 = fmaxf(mt0, __shfl_xor_sync(0xffffffffu, mt0, 1));
        mt0 = fmaxf(mt0, __shfl_xor_sync(0xffffffffu, mt0, 2));
        mt1 = fmaxf(mt1, __shfl_xor_sync(0xffffffffu, mt1, 1));
        mt1 = fmaxf(mt1, __shfl_xor_sync(0xffffffffu, mt1, 2));
        const float mn0 = fmaxf(m0, mt0);
        const float mn1 = fmaxf(m1, mt1);
        const float sc0 = __expf(m0 - mn0);
        const float sc1 = __expf(m1 - mn1);
        float ls0 = 0.f, ls1 = 0.f;
        #pragma unroll
        for (int nt = 0; nt < 8; nt++) {
            sacc[nt][0] = __expf(sacc[nt][0] - mn0);
            sacc[nt][1] = __expf(sacc[nt][1] - mn0);
            sacc[nt][2] = __expf(sacc[nt][2] - mn1);
            sacc[nt][3] = __expf(sacc[nt][3] - mn1);
            ls0 += sacc[nt][0] + sacc[nt][1];
            ls1 += sacc[nt][2] + sacc[nt][3];
        }
        l0 = l0 * sc0 + ls0;
        l1 = l1 * sc1 + ls1;
        m0 = mn0; m1 = mn1;
        #pragma unroll
        for (int nt = 0; nt < 8; nt++) {
            oacc[nt][0] *= sc0; oacc[nt][1] *= sc0;
            oacc[nt][2] *= sc1; oacc[nt][3] *= sc1;
        }

        // O += P @ (Vh + Vm), P hi-only fp16 (err ~2.8e-4, softmax-normalized)
        #pragma unroll
        for (int ks = 0; ks < 4; ks++) {
            const uint32_t pah0 = hpack(__float2half_rn(sacc[2 * ks][0]),
                                        __float2half_rn(sacc[2 * ks][1]));
            const uint32_t pah1 = hpack(__float2half_rn(sacc[2 * ks][2]),
                                        __float2half_rn(sacc[2 * ks][3]));
            const uint32_t pah2 = hpack(__float2half_rn(sacc[2 * ks + 1][0]),
                                        __float2half_rn(sacc[2 * ks + 1][1]));
            const uint32_t pah3 = hpack(__float2half_rn(sacc[2 * ks + 1][2]),
                                        __float2half_rn(sacc[2 * ks + 1][3]));
            #pragma unroll
            for (int nt = 0; nt < 8; nt++) {
                const int vo = (nt * 8 + lq) * FST + ks * 8 + lc;
                const uint32_t vh0 = VH[vo], vh1 = VH[vo + 4];
                const uint32_t vm0 = VM[vo], vm1 = VM[vo + 4];
                mma_f16(oacc[nt][0], oacc[nt][1], oacc[nt][2], oacc[nt][3],
                        pah0, pah1, pah2, pah3, vm0, vm1);
                mma_f16(oacc[nt][0], oacc[nt][1], oacc[nt][2], oacc[nt][3],
                        pah0, pah1, pah2, pah3, vh0, vh1);
            }
        }
    }

    l0 += __shfl_xor_sync(0xffffffffu, l0, 1);
    l0 += __shfl_xor_sync(0xffffffffu, l0, 2);
    l1 += __shfl_xor_sync(0xffffffffu, l1, 1);
    l1 += __shfl_xor_sync(0xffffffffu, l1, 2);
    const float inv0 = 1.f / l0;
    const float inv1 = 1.f / l1;

    const size_t ob = ((size_t)(b * Sseq + t * 128 + warp * 16 + lq)) * 1024 + h * 64;
    #pragma unroll
    for (int nt = 0; nt < 8; nt++) {
        const int cb = nt * 8 + 2 * lc;
        float v00 = oacc[nt][0] * inv0, v01 = oacc[nt][1] * inv0;
        float v10 = oacc[nt][2] * inv1, v11 = oacc[nt][3] * inv1;
        __half h00, h01, h10, h11, m00, m01, m10, m11;
        hsplit(v00, h00, m00); hsplit(v01, h01, m01);
        hsplit(v10, h10, m10); hsplit(v11, h11, m11);
        *(uint32_t*)&Oh[ob + cb] = hpack(h00, h01);
        *(uint32_t*)&Oh[ob + 8 * 1024 + cb] = hpack(h10, h11);
        *(uint32_t*)&Om[ob + cb] = hpack(m00, m01);
        *(uint32_t*)&Om[ob + 8 * 1024 + cb] = hpack(m10, m11);
    }
}

// ---------------------------------------------------------------------------
extern "C" void kernel_launch(void* const* d_in, const int* in_sizes, int n_in,
                              void* d_out, int out_size)
{
    (void)in_sizes; (void)n_in; (void)out_size;
    const float* attend_from = (const float*)d_in[0];
    const float* attend_to   = (const float*)d_in[1];
    const float* w_q   = (const float*)d_in[2];
    const float* b_q   = (const float*)d_in[3];
    const float* w_kv  = (const float*)d_in[4];
    const float* b_kv  = (const float*)d_in[5];
    const float* w_out = (const float*)d_in[6];
    const float* b_out = (const float*)d_in[7];
    float* out = (float*)d_out;

    __half *afh, *afm, *ath, *atm, *wqh, *wqm, *wkvh, *wkvm, *woh, *wom;
    __half *qh, *qm, *kh, *km, *vth, *vtm, *oh, *om;
    cudaGetSymbolAddress((void**)&afh, g_Afh);
    cudaGetSymbolAddress((void**)&afm, g_Afm);
    cudaGetSymbolAddress((void**)&ath, g_Ath);
    cudaGetSymbolAddress((void**)&atm, g_Atm);
    cudaGetSymbolAddress((void**)&wqh, g_Wqh);
    cudaGetSymbolAddress((void**)&wqm, g_Wqm);
    cudaGetSymbolAddress((void**)&wkvh, g_Wkvh);
    cudaGetSymbolAddress((void**)&wkvm, g_Wkvm);
    cudaGetSymbolAddress((void**)&woh, g_Woh);
    cudaGetSymbolAddress((void**)&wom, g_Wom);
    cudaGetSymbolAddress((void**)&qh, g_Qh);
    cudaGetSymbolAddress((void**)&qm, g_Qm);
    cudaGetSymbolAddress((void**)&kh, g_Kh);
    cudaGetSymbolAddress((void**)&km, g_Km);
    cudaGetSymbolAddress((void**)&vth, g_Vth);
    cudaGetSymbolAddress((void**)&vtm, g_Vtm);
    cudaGetSymbolAddress((void**)&oh, g_Oh);
    cudaGetSymbolAddress((void**)&om, g_Om);

    cudaFuncSetAttribute(qkv_gemm_kernel,
                         cudaFuncAttributeMaxDynamicSharedMemorySize, GEMM_SMEM);
    cudaFuncSetAttribute(out_gemm_kernel,
                         cudaFuncAttributeMaxDynamicSharedMemorySize, GEMM_SMEM);
    cudaFuncSetAttribute(flash_mma_kernel,
                         cudaFuncAttributeMaxDynamicSharedMemorySize, FLASH_SMEM);

    // 0) pre-split activations, split+transpose weights
    {
        const int nA = Mrows * Fdim / 4;
        asplit_kernel<<<(nA + 255) / 256, 256>>>(attend_from, afh, afm, nA);
        asplit_kernel<<<(nA + 255) / 256, 256>>>(attend_to,   ath, atm, nA);
        wsplit_kernel<<<dim3(32, 32), 256>>>(w_q,   wqh,  wqm,  1024, 1024);
        wsplit_kernel<<<dim3(32, 64), 256>>>(w_kv,  wkvh, wkvm, 1024, 2048);
        wsplit_kernel<<<dim3(32, 32), 256>>>(w_out, woh,  wom,  1024, 1024);
    }

    // 1) merged Q + KV projection (128 Q CTAs + 256 KV CTAs)
    qkv_gemm_kernel<<<384, 256, GEMM_SMEM>>>(
        afh, afm, ath, atm, wqh, wqm, wkvh, wkvm, b_q, b_kv,
        qh, qm, kh, km, vth, vtm);

    // 2) flash attention (row s=0 via row0_kernel)
    {
        dim3 grid(Sseq / 128, Hh, Bsz);
        flash_mma_kernel<<<grid, 256, FLASH_SMEM>>>(
            qh, qm, kh, km, vth, vtm, oh, om);
    }

    // 2b) exact fix-up for fully-masked row s=0
    {
        dim3 grid(1024, Bsz);
        row0_kernel<<<grid, 256>>>(vth, vtm, oh, om);
    }

    // 3) output projection (2-MMA)
    {
        dim3 grid(Fdim / 256, Mrows / 128);
        out_gemm_kernel<<<grid, 256, GEMM_SMEM>>>(oh, om, woh, wom, b_out, out);
    }
}

// round 15
// speedup vs baseline: 1.4096x; 1.1859x over previous
#include <cuda_runtime.h>
#include <cuda_fp16.h>
#include <math.h>
#include <stdint.h>

// Problem constants (fixed shapes)
constexpr int Bsz  = 2;
constexpr int Sseq = 2048;
constexpr int Fdim = 1024;
constexpr int Hh   = 16;
constexpr int Dh   = 64;
constexpr int Mrows = Bsz * Sseq;   // 4096

// Scratch (device globals, allocation-free). Operands live as fp16 planes:
// hi = fp16(x), mid = fp16(x - hi); hi+mid recovers fp32 to ~2^-22.
__device__ __half g_Afh[(size_t)Mrows * Fdim];
__device__ __half g_Afm[(size_t)Mrows * Fdim];
__device__ __half g_Ath[(size_t)Mrows * Fdim];
__device__ __half g_Atm[(size_t)Mrows * Fdim];
__device__ __half g_Wqh[(size_t)Fdim * Fdim];      // w_q^T  [n][k]
__device__ __half g_Wqm[(size_t)Fdim * Fdim];
__device__ __half g_Wkvh[(size_t)2 * Fdim * Fdim]; // w_kv^T [n][k]
__device__ __half g_Wkvm[(size_t)2 * Fdim * Fdim];
__device__ __half g_Woh[(size_t)Fdim * Fdim];      // w_out^T [n][k] (hi only used)
__device__ __half g_Wom[(size_t)Fdim * Fdim];
__device__ __half g_Qh[(size_t)Mrows * Fdim];
__device__ __half g_Qm[(size_t)Mrows * Fdim];
__device__ __half g_Kh[(size_t)Mrows * Fdim];
__device__ __half g_Km[(size_t)Mrows * Fdim];
__device__ __half g_Vth[(size_t)Mrows * Fdim];     // V^T [b][h][d][s]
__device__ __half g_Vtm[(size_t)Mrows * Fdim];     // used by row0 only
__device__ __half g_Oh[(size_t)Mrows * Fdim];
__device__ __half g_Om[(size_t)Mrows * Fdim];

// ---------------------------------------------------------------------------
// PTX helpers
// ---------------------------------------------------------------------------
__device__ __forceinline__ void cp_async16(uint32_t saddr, const void* gptr) {
    asm volatile("cp.async.cg.shared.global [%0], [%1], 16;"
                 :: "r"(saddr), "l"(gptr));
}
__device__ __forceinline__ void cp_commit() {
    asm volatile("cp.async.commit_group;");
}
__device__ __forceinline__ void cp_wait0() {
    asm volatile("cp.async.wait_group 0;");
}

__device__ __forceinline__ void mma_f16(
    float& d0, float& d1, float& d2, float& d3,
    uint32_t a0, uint32_t a1, uint32_t a2, uint32_t a3,
    uint32_t b0, uint32_t b1)
{
    asm volatile(
        "mma.sync.aligned.m16n8k16.row.col.f32.f16.f16.f32 "
        "{%0,%1,%2,%3},{%4,%5,%6,%7},{%8,%9},{%0,%1,%2,%3};"
        : "+f"(d0), "+f"(d1), "+f"(d2), "+f"(d3)
        : "r"(a0), "r"(a1), "r"(a2), "r"(a3), "r"(b0), "r"(b1));
}

__device__ __forceinline__ void hsplit(float v, __half& h, __half& m) {
    h = __float2half_rn(v);
    m = __float2half_rn(v - __half2float(h));
}
__device__ __forceinline__ uint32_t hpack(__half lo, __half hi) {
    __half2 t;
    t.x = lo; t.y = hi;
    return *reinterpret_cast<uint32_t*>(&t);
}

// ---------------------------------------------------------------------------
// Pre-pass: elementwise split (no transpose) for activations [M][K].
// ---------------------------------------------------------------------------
__global__ __launch_bounds__(256) void asplit_kernel(
    const float* __restrict__ src, __half* __restrict__ hi,
    __half* __restrict__ mid, int n4)
{
    const int i = blockIdx.x * 256 + threadIdx.x;
    if (i >= n4) return;
    float4 v = ((const float4*)src)[i];
    __half h0, h1, h2, h3, m0, m1, m2, m3;
    hsplit(v.x, h0, m0); hsplit(v.y, h1, m1);
    hsplit(v.z, h2, m2); hsplit(v.w, h3, m3);
    ((uint2*)hi)[i]  = make_uint2(hpack(h0, h1), hpack(h2, h3));
    ((uint2*)mid)[i] = make_uint2(hpack(m0, m1), hpack(m2, m3));
}

// Pre-pass: split + transpose weights w[k][n] -> planes [n][k].
__global__ __launch_bounds__(256) void wsplit_kernel(
    const float* __restrict__ w, __half* __restrict__ th,
    __half* __restrict__ tm, int K, int N)
{
    __shared__ float ts[32][33];
    const int k0 = blockIdx.x * 32;
    const int n0 = blockIdx.y * 32;
    const int tx = threadIdx.x & 31;
    const int ty = threadIdx.x >> 5;
    #pragma unroll
    for (int i = 0; i < 4; i++)
        ts[ty + 8 * i][tx] = w[(size_t)(k0 + ty + 8 * i) * N + n0 + tx];
    __syncthreads();
    #pragma unroll
    for (int i = 0; i < 4; i++) {
        float v = ts[tx][ty + 8 * i];
        __half h, m;
        hsplit(v, h, m);
        const size_t o = (size_t)(n0 + ty + 8 * i) * K + k0 + tx;
        th[o] = h;
        tm[o] = m;
    }
}

// Row-0 fix: fully-masked row -> uniform softmax -> mean of V rows.
__global__ __launch_bounds__(256) void row0_kernel(
    const __half* __restrict__ Vth, const __half* __restrict__ Vtm,
    __half* __restrict__ Oh, __half* __restrict__ Om)
{
    __shared__ float red[256];
    const int f = blockIdx.x;
    const int b = blockIdx.y;
    const int h = f >> 6, d = f & 63;
    const size_t base = ((size_t)(b * 16 + h) * 64 + d) * 2048;
    float s = 0.f;
    for (int i = threadIdx.x; i < 2048; i += 256)
        s += __half2float(Vth[base + i]) + __half2float(Vtm[base + i]);
    red[threadIdx.x] = s;
    __syncthreads();
    for (int o = 128; o > 0; o >>= 1) {
        if (threadIdx.x < o) red[threadIdx.x] += red[threadIdx.x + o];
        __syncthreads();
    }
    if (threadIdx.x == 0) {
        const float v = red[0] * (1.f / 2048.f);
        __half hh, mm;
        hsplit(v, hh, mm);
        const size_t o = (size_t)(b * Sseq) * 1024 + f;
        Oh[o] = hh;
        Om[o] = mm;
    }
}

// ---------------------------------------------------------------------------
// fp16 GEMM core: C[M,N] = A[M,1024] @ W^T[n][k] (+bias via epilogue).
// CTA tile 128x256, BK=32, 256 threads, 8 warps of 64x64 warp tiles,
// 2-stage cp.async pipeline.
// NMMA=3: Am·Bh + Ah·Bm + Ah·Bh (err ~2^-22)
// NMMA=2: Am·Bh + Ah·Bh          (B uncorrected, ~2.8e-4)
// NMMA=1: Ah·Bh                  (both uncorrected, ~4e-4)
// Unused mid planes are neither loaded nor read.
// ---------------------------------------------------------------------------
constexpr int SW   = 20;                    // words per row (16 data + 4 pad)
constexpr int PLWA = 128 * SW;              // 2560 words per A plane
constexpr int PLWB = 256 * SW;              // 5120 words per B plane
constexpr int STAGE_W = 2 * PLWA + 2 * PLWB;        // 15360 words
constexpr int GEMM_SMEM = 2 * STAGE_W * 4;          // 122880 B

template <int NMMA, typename EPI>
__device__ __forceinline__ void gemm_mainloop(
    const __half* __restrict__ Ah, const __half* __restrict__ Am,
    const __half* __restrict__ Bh, const __half* __restrict__ Bm,
    int m0, int n0, uint32_t* smw, EPI epi)
{
    const uint32_t sbase = (uint32_t)__cvta_generic_to_shared(smw);
    const int tid  = threadIdx.x;
    const int warp = tid >> 5;
    const int lane = tid & 31;
    const int rbase = (warp & 1) * 64;        // 2 m-slabs of 64
    const int cbase = (warp >> 1) * 64;       // 4 n-slabs of 64
    const int lq  = lane >> 2;      // 0..7
    const int lc  = lane & 3;       // 0..3

    float acc[4][8][4];
    #pragma unroll
    for (int i = 0; i < 4; i++)
        #pragma unroll
        for (int j = 0; j < 8; j++)
            #pragma unroll
            for (int r = 0; r < 4; r++) acc[i][j][r] = 0.f;

    auto load_tile = [&](int kt, int st) {
        const int k0 = kt * 32;
        const uint32_t base = sbase + (uint32_t)(st * STAGE_W) * 4u;
        #pragma unroll
        for (int it = 0; it < 2; it++) {
            const int slot = it * 256 + tid;
            const int row = slot >> 2, c4 = slot & 3;
            const uint32_t so = (uint32_t)(row * SW + c4 * 4) * 4u;
            const size_t ga = (size_t)(m0 + row) * 1024 + k0 + c4 * 8;
            cp_async16(base + so, &Ah[ga]);
            if (NMMA >= 2)
                cp_async16(base + (uint32_t)(PLWA * 4) + so, &Am[ga]);
        }
        #pragma unroll
        for (int it = 0; it < 4; it++) {
            const int slot = it * 256 + tid;
            const int row = slot >> 2, c4 = slot & 3;
            const uint32_t so = (uint32_t)(row * SW + c4 * 4) * 4u;
            const size_t gb = (size_t)(n0 + row) * 1024 + k0 + c4 * 8;
            cp_async16(base + (uint32_t)(2 * PLWA * 4) + so, &Bh[gb]);
            if (NMMA == 3)
                cp_async16(base + (uint32_t)((2 * PLWA + PLWB) * 4) + so, &Bm[gb]);
        }
    };

    load_tile(0, 0);
    cp_commit();

    for (int kt = 0; kt < 32; kt++) {
        cp_wait0();
        __syncthreads();   // also orders compute(kt-1) before loads(kt+1)
        if (kt + 1 < 32) { load_tile(kt + 1, (kt + 1) & 1); cp_commit(); }

        const uint32_t* AH = smw + (kt & 1) * STAGE_W;
        const uint32_t* AM = AH + PLWA;
        const uint32_t* BH = AH + 2 * PLWA;
        const uint32_t* BM = AH + 2 * PLWA + PLWB;

        #pragma unroll
        for (int ks = 0; ks < 2; ks++) {
            const int kk2 = ks * 8;
            uint32_t ah[4][4], am[4][4];
            #pragma unroll
            for (int mi = 0; mi < 4; mi++) {
                const int rr = rbase + mi * 16 + lq;
                const int o0 = rr * SW + kk2 + lc;
                const int o1 = (rr + 8) * SW + kk2 + lc;
                ah[mi][0] = AH[o0];
                ah[mi][1] = AH[o1];
                ah[mi][2] = AH[o0 + 4];
                ah[mi][3] = AH[o1 + 4];
                if (NMMA >= 2) {
                    am[mi][0] = AM[o0];
                    am[mi][1] = AM[o1];
                    am[mi][2] = AM[o0 + 4];
                    am[mi][3] = AM[o1 + 4];
                }
            }
            #pragma unroll
            for (int njp = 0; njp < 2; njp++) {
                uint32_t bh[4][2], bm[4][2];
                #pragma unroll
                for (int j = 0; j < 4; j++) {
                    const int cc = cbase + (njp * 4 + j) * 8 + lq;
                    const int o = cc * SW + kk2 + lc;
                    bh[j][0] = BH[o];
                    bh[j][1] = BH[o + 4];
                    if (NMMA == 3) { bm[j][0] = BM[o]; bm[j][1] = BM[o + 4]; }
                }
                #pragma unroll
                for (int mi = 0; mi < 4; mi++)
                    #pragma unroll
                    for (int j = 0; j < 4; j++) {
                        const int nj = njp * 4 + j;
                        if (NMMA >= 2)
                            mma_f16(acc[mi][nj][0], acc[mi][nj][1],
                                    acc[mi][nj][2], acc[mi][nj][3],
                                    am[mi][0], am[mi][1], am[mi][2], am[mi][3],
                                    bh[j][0], bh[j][1]);
                        if (NMMA == 3)
                            mma_f16(acc[mi][nj][0], acc[mi][nj][1],
                                    acc[mi][nj][2], acc[mi][nj][3],
                                    ah[mi][0], ah[mi][1], ah[mi][2], ah[mi][3],
                                    bm[j][0], bm[j][1]);
                        mma_f16(acc[mi][nj][0], acc[mi][nj][1],
                                acc[mi][nj][2], acc[mi][nj][3],
                                ah[mi][0], ah[mi][1], ah[mi][2], ah[mi][3],
                                bh[j][0], bh[j][1]);
                    }
            }
        }
    }
    __syncthreads();
    epi(acc, rbase, cbase, lq, lc);
}

// QKV epilogue body shared by the Q/K (3-MMA) and V (1-MMA) instantiations.
template <typename ACC>
__device__ __forceinline__ void qkv_epilogue(
    ACC& acc, int bx, int m0, int n0, int ncol, int is_v,
    const float* bias, int rbase, int cbase, int lq, int lc,
    __half* Qh, __half* Qm, __half* Kh, __half* Km,
    __half* Vth, __half* Vtm)
{
    #pragma unroll
    for (int mi = 0; mi < 4; mi++) {
        const int r0 = m0 + rbase + mi * 16 + lq;
        #pragma unroll
        for (int nj = 0; nj < 8; nj++) {
            const int col = ncol + cbase + nj * 8 + lc * 2;
            const float b0 = bias[n0 - ncol + col];
            const float b1 = bias[n0 - ncol + col + 1];
            float v00 = acc[mi][nj][0] + b0;
            float v01 = acc[mi][nj][1] + b1;
            float v10 = acc[mi][nj][2] + b0;
            float v11 = acc[mi][nj][3] + b1;
            __half h00, h01, h10, h11, q00, q01, q10, q11;
            hsplit(v00, h00, q00); hsplit(v01, h01, q01);
            hsplit(v10, h10, q10); hsplit(v11, h11, q11);
            if (!is_v) {
                __half* Dh = (bx < 128) ? Qh : Kh;
                __half* Dm = (bx < 128) ? Qm : Km;
                const size_t o0 = (size_t)r0 * 1024 + col;
                const size_t o1 = (size_t)(r0 + 8) * 1024 + col;
                *(uint32_t*)&Dh[o0] = hpack(h00, h01);
                *(uint32_t*)&Dh[o1] = hpack(h10, h11);
                *(uint32_t*)&Dm[o0] = hpack(q00, q01);
                *(uint32_t*)&Dm[o1] = hpack(q10, q11);
            } else {
                // V transposed: [b][h][d][s]
                const int h = col >> 6, d = col & 63;
                const int bl0 = r0 >> 11, s0 = r0 & 2047;
                const int bl1 = (r0 + 8) >> 11, s1 = (r0 + 8) & 2047;
                const size_t i00 = ((size_t)(bl0 * 16 + h) * 64 + d) * 2048 + s0;
                const size_t i10 = ((size_t)(bl1 * 16 + h) * 64 + d) * 2048 + s1;
                Vth[i00] = h00;          Vtm[i00] = q00;
                Vth[i00 + 2048] = h01;   Vtm[i00 + 2048] = q01;
                Vth[i10] = h10;          Vtm[i10] = q10;
                Vth[i10 + 2048] = h11;   Vtm[i10 + 2048] = q11;
            }
        }
    }
}

// Merged Q + KV projection. grid.x = 384 (Q: 128, K: 128, V: 128 CTAs).
// Q/K tiles: 3-MMA (logit path). V tiles: 1-MMA (linear path).
__global__ __launch_bounds__(256, 1) void qkv_gemm_kernel(
    const __half* __restrict__ Afh, const __half* __restrict__ Afm,
    const __half* __restrict__ Ath, const __half* __restrict__ Atm,
    const __half* __restrict__ Wqh, const __half* __restrict__ Wqm,
    const __half* __restrict__ Wkvh, const __half* __restrict__ Wkvm,
    const float* __restrict__ bq, const float* __restrict__ bkv,
    __half* __restrict__ Qh, __half* __restrict__ Qm,
    __half* __restrict__ Kh, __half* __restrict__ Km,
    __half* __restrict__ Vth, __half* __restrict__ Vtm)
{
    extern __shared__ uint32_t smw[];
    const int bx = blockIdx.x;

    const __half *Ah, *Am, *Bh, *Bm;
    const float* bias;
    int m0, n0, is_v = 0, ncol;
    if (bx < 128) {
        Ah = Afh; Am = Afm; Bh = Wqh; Bm = Wqm; bias = bq;
        m0 = (bx >> 2) * 128; n0 = (bx & 3) * 256; ncol = n0;
    } else {
        const int bxx = bx - 128;
        Ah = Ath; Am = Atm; Bh = Wkvh; Bm = Wkvm; bias = bkv;
        m0 = (bxx >> 3) * 128; n0 = (bxx & 7) * 256;
        if (n0 < 1024) { ncol = n0; }
        else           { ncol = n0 - 1024; is_v = 1; }
    }

    if (!is_v) {
        gemm_mainloop<3>(Ah, Am, Bh, Bm, m0, n0, smw,
            [&](float (&acc)[4][8][4], int rbase, int cbase, int lq, int lc) {
                qkv_epilogue(acc, bx, m0, n0, ncol, 0, bias, rbase, cbase,
                             lq, lc, Qh, Qm, Kh, Km, Vth, Vtm);
            });
    } else {
        gemm_mainloop<1>(Ah, Am, Bh, Bm, m0, n0, smw,
            [&](float (&acc)[4][8][4], int rbase, int cbase, int lq, int lc) {
                qkv_epilogue(acc, bx, m0, n0, ncol, 1, bias, rbase, cbase,
                             lq, lc, Qh, Qm, Kh, Km, Vth, Vtm);
            });
    }
}

// Output projection: out = O @ w_out + b_out (fp32 store). 1-MMA path.
__global__ __launch_bounds__(256, 1) void out_gemm_kernel(
    const __half* __restrict__ Ah, const __half* __restrict__ Am,
    const __half* __restrict__ Bh, const __half* __restrict__ Bm,
    const float* __restrict__ bias, float* __restrict__ C)
{
    extern __shared__ uint32_t smw[];
    const int m0 = blockIdx.y * 128;
    const int n0 = blockIdx.x * 256;
    gemm_mainloop<1>(Ah, Am, Bh, Bm, m0, n0, smw,
        [&](float (&acc)[4][8][4], int rbase, int cbase, int lq, int lc) {
            #pragma unroll
            for (int mi = 0; mi < 4; mi++) {
                const int r0 = m0 + rbase + mi * 16 + lq;
                #pragma unroll
                for (int nj = 0; nj < 8; nj++) {
                    const int col = n0 + cbase + nj * 8 + lc * 2;
                    const float b0 = bias[col], b1 = bias[col + 1];
                    *(float2*)&C[(size_t)r0 * Fdim + col] =
                        make_float2(acc[mi][nj][0] + b0, acc[mi][nj][1] + b1);
                    *(float2*)&C[(size_t)(r0 + 8) * Fdim + col] =
                        make_float2(acc[mi][nj][2] + b0, acc[mi][nj][3] + b1);
                }
            }
        });
}

// ---------------------------------------------------------------------------
// fp16 flash attention. Br=128, Bc=64, d=64. 8 warps, 16 q-rows each.
// S: 3 MMAs (logit-accurate). O: 1 MMA (P hi x V hi; linear path).
// Only 3 smem planes (Kh, Km, Vh), double-buffered.
// Mask: z >= s -> -1e12f. CTA t: 2t+2 tiles; row 0 via row0_kernel.
// ---------------------------------------------------------------------------
constexpr int FST = 36;
constexpr int FTW = 64 * FST;
constexpr int FLASH_SMEM = 6 * FTW * 4;   // 3 planes x 2 stages = 55296 B

__global__ __launch_bounds__(256) void flash_mma_kernel(
    const __half* __restrict__ Qh, const __half* __restrict__ Qm,
    const __half* __restrict__ Kh, const __half* __restrict__ Km,
    const __half* __restrict__ Vth,
    __half* __restrict__ Oh, __half* __restrict__ Om)
{
    extern __shared__ uint32_t smw[];
    const uint32_t sbase = (uint32_t)__cvta_generic_to_shared(smw);

    const int t = 15 - (int)blockIdx.x;
    const int h = blockIdx.y;
    const int b = blockIdx.z;
    const int tid  = threadIdx.x;
    const int warp = tid >> 5;
    const int lane = tid & 31;
    const int lq  = lane >> 2;
    const int lc  = lane & 3;

    auto plane = [&](int p, int st) { return (uint32_t)((p * 2 + st) * FTW); };

    auto load_kv = [&](int kc, int st) {
        #pragma unroll
        for (int it = 0; it < 2; it++) {
            const int slot = it * 256 + tid;
            const int row = slot >> 3;
            const int c8 = slot & 7;
            const uint32_t so = (uint32_t)(row * FST + c8 * 4) * 4u;
            const size_t gk = (size_t)(b * Sseq + kc * 64 + row) * 1024 + h * 64 + c8 * 8;
            cp_async16(sbase + (plane(0, st)) * 4u + so, &Kh[gk]);
            cp_async16(sbase + (plane(1, st)) * 4u + so, &Km[gk]);
            const size_t gv = ((size_t)(b * 16 + h) * 64 + row) * 2048 + kc * 64 + c8 * 8;
            cp_async16(sbase + (plane(2, st)) * 4u + so, &Vth[gv]);
        }
    };

    load_kv(0, 0);
    cp_commit();

    const uint32_t* Qh32 = (const uint32_t*)Qh;
    const uint32_t* Qm32 = (const uint32_t*)Qm;
    uint32_t qh[4][4], qm[4][4];
    {
        const int qrow = b * Sseq + t * 128 + warp * 16 + lq;
        const size_t qb0 = (size_t)qrow * 512 + h * 32;
        const size_t qb1 = qb0 + 8 * 512;
        #pragma unroll
        for (int ks = 0; ks < 4; ks++) {
            const int o = ks * 8 + lc;
            qh[ks][0] = Qh32[qb0 + o];     qm[ks][0] = Qm32[qb0 + o];
            qh[ks][1] = Qh32[qb1 + o];     qm[ks][1] = Qm32[qb1 + o];
            qh[ks][2] = Qh32[qb0 + o + 4]; qm[ks][2] = Qm32[qb0 + o + 4];
            qh[ks][3] = Qh32[qb1 + o + 4]; qm[ks][3] = Qm32[qb1 + o + 4];
        }
    }

    float oacc[8][4];
    #pragma unroll
    for (int nt = 0; nt < 8; nt++)
        #pragma unroll
        for (int r = 0; r < 4; r++) oacc[nt][r] = 0.f;
    float m0 = -3.0e38f, m1 = -3.0e38f, l0 = 0.f, l1 = 0.f;

    const int row0 = t * 128 + warp * 16 + lq;
    const int row1 = row0 + 8;
    const int nkc = 2 * t + 2;

    for (int kc = 0; kc < nkc; kc++) {
        cp_wait0();
        __syncthreads();
        if (kc + 1 < nkc) { load_kv(kc + 1, (kc + 1) & 1); cp_commit(); }

        const int st = kc & 1;
        const uint32_t* KH = smw + plane(0, st);
        const uint32_t* KM = smw + plane(1, st);
        const uint32_t* VH = smw + plane(2, st);

        float sacc[8][4];
        #pragma unroll
        for (int nt = 0; nt < 8; nt++)
            #pragma unroll
            for (int r = 0; r < 4; r++) sacc[nt][r] = 0.f;

        #pragma unroll
        for (int ks = 0; ks < 4; ks++) {
            #pragma unroll
            for (int nt = 0; nt < 8; nt++) {
                const int ko = (nt * 8 + lq) * FST + ks * 8 + lc;
                const uint32_t bh0 = KH[ko], bh1 = KH[ko + 4];
                const uint32_t bm0 = KM[ko], bm1 = KM[ko + 4];
                mma_f16(sacc[nt][0], sacc[nt][1], sacc[nt][2], sacc[nt][3],
                        qm[ks][0], qm[ks][1], qm[ks][2], qm[ks][3], bh0, bh1);
                mma_f16(sacc[nt][0], sacc[nt][1], sacc[nt][2], sacc[nt][3],
                        qh[ks][0], qh[ks][1], qh[ks][2], qh[ks][3], bm0, bm1);
                mma_f16(sacc[nt][0], sacc[nt][1], sacc[nt][2], sacc[nt][3],
                        qh[ks][0], qh[ks][1], qh[ks][2], qh[ks][3], bh0, bh1);
            }
        }

        #pragma unroll
        for (int nt = 0; nt < 8; nt++) {
            const int cb = kc * 64 + nt * 8 + 2 * lc;
            if (cb     >= row0) sacc[nt][0] = -1.0e12f;
            if (cb + 1 >= row0) sacc[nt][1] = -1.0e12f;
            if (cb     >= row1) sacc[nt][2] = -1.0e12f;
            if (cb + 1 >= row1) sacc[nt][3] = -1.0e12f;
        }

        float mt0 = -3.0e38f, mt1 = -3.0e38f;
        #pragma unroll
        for (int nt = 0; nt < 8; nt++) {
            mt0 = fmaxf(mt0, fmaxf(sacc[nt][0], sacc[nt][1]));
            mt1 = fmaxf(mt1, fmaxf(sacc[nt][2], sacc[nt][3]));
        }
        mt0 = fmaxf(mt0, __shfl_xor_sync(0xffffffffu, mt0, 1));
        mt0 = fmaxf(mt0, __shfl_xor_sync(0xffffffffu, mt0, 2));
        mt1 = fmaxf(mt1, __shfl_xor_sync(0xffffffffu, mt1, 1));
        mt1 = fmaxf(mt1, __shfl_xor_sync(0xffffffffu, mt1, 2));
        const float mn0 = fmaxf(m0, mt0);
        const float mn1 = fmaxf(m1, mt1);
        const float sc0 = __expf(m0 - mn0);
        const float sc1 = __expf(m1 - mn1);
        float ls0 = 0.f, ls1 = 0.f;
        #pragma unroll
        for (int nt = 0; nt < 8; nt++) {
            sacc[nt][0] = __expf(sacc[nt][0] - mn0);
            sacc[nt][1] = __expf(sacc[nt][1] - mn0);
            sacc[nt][2] = __expf(sacc[nt][2] - mn1);
            sacc[nt][3] = __expf(sacc[nt][3] - mn1);
            ls0 += sacc[nt][0] + sacc[nt][1];
            ls1 += sacc[nt][2] + sacc[nt][3];
        }
        l0 = l0 * sc0 + ls0;
        l1 = l1 * sc1 + ls1;
        m0 = mn0; m1 = mn1;
        #pragma unroll
        for (int nt = 0; nt < 8; nt++) {
            oacc[nt][0] *= sc0; oacc[nt][1] *= sc0;
            oacc[nt][2] *= sc1; oacc[nt][3] *= sc1;
        }

        // O += P_hi @ V_hi (single MMA; linear path)
        #pragma unroll
        for (int ks = 0; ks < 4; ks++) {
            const uint32_t pah0 = hpack(__float2half_rn(sacc[2 * ks][0]),
                                        __float2half_rn(sacc[2 * ks][1]));
            const uint32_t pah1 = hpack(__float2half_rn(sacc[2 * ks][2]),
                                        __float2half_rn(sacc[2 * ks][3]));
            const uint32_t pah2 = hpack(__float2half_rn(sacc[2 * ks + 1][0]),
                                        __float2half_rn(sacc[2 * ks + 1][1]));
            const uint32_t pah3 = hpack(__float2half_rn(sacc[2 * ks + 1][2]),
                                        __float2half_rn(sacc[2 * ks + 1][3]));
            #pragma unroll
            for (int nt = 0; nt < 8; nt++) {
                const int vo = (nt * 8 + lq) * FST + ks * 8 + lc;
                const uint32_t vh0 = VH[vo], vh1 = VH[vo + 4];
                mma_f16(oacc[nt][0], oacc[nt][1], oacc[nt][2], oacc[nt][3],
                        pah0, pah1, pah2, pah3, vh0, vh1);
            }
        }
    }

    l0 += __shfl_xor_sync(0xffffffffu, l0, 1);
    l0 += __shfl_xor_sync(0xffffffffu, l0, 2);
    l1 += __shfl_xor_sync(0xffffffffu, l1, 1);
    l1 += __shfl_xor_sync(0xffffffffu, l1, 2);
    const float inv0 = 1.f / l0;
    const float inv1 = 1.f / l1;

    const size_t ob = ((size_t)(b * Sseq + t * 128 + warp * 16 + lq)) * 1024 + h * 64;
    #pragma unroll
    for (int nt = 0; nt < 8; nt++) {
        const int cb = nt * 8 + 2 * lc;
        float v00 = oacc[nt][0] * inv0, v01 = oacc[nt][1] * inv0;
        float v10 = oacc[nt][2] * inv1, v11 = oacc[nt][3] * inv1;
        __half h00, h01, h10, h11, m00, m01, m10, m11;
        hsplit(v00, h00, m00); hsplit(v01, h01, m01);
        hsplit(v10, h10, m10); hsplit(v11, h11, m11);
        *(uint32_t*)&Oh[ob + cb] = hpack(h00, h01);
        *(uint32_t*)&Oh[ob + 8 * 1024 + cb] = hpack(h10, h11);
        *(uint32_t*)&Om[ob + cb] = hpack(m00, m01);
        *(uint32_t*)&Om[ob + 8 * 1024 + cb] = hpack(m10, m11);
    }
}

// ---------------------------------------------------------------------------
extern "C" void kernel_launch(void* const* d_in, const int* in_sizes, int n_in,
                              void* d_out, int out_size)
{
    (void)in_sizes; (void)n_in; (void)out_size;
    const float* attend_from = (const float*)d_in[0];
    const float* attend_to   = (const float*)d_in[1];
    const float* w_q   = (const float*)d_in[2];
    const float* b_q   = (const float*)d_in[3];
    const float* w_kv  = (const float*)d_in[4];
    const float* b_kv  = (const float*)d_in[5];
    const float* w_out = (const float*)d_in[6];
    const float* b_out = (const float*)d_in[7];
    float* out = (float*)d_out;

    __half *afh, *afm, *ath, *atm, *wqh, *wqm, *wkvh, *wkvm, *woh, *wom;
    __half *qh, *qm, *kh, *km, *vth, *vtm, *oh, *om;
    cudaGetSymbolAddress((void**)&afh, g_Afh);
    cudaGetSymbolAddress((void**)&afm, g_Afm);
    cudaGetSymbolAddress((void**)&ath, g_Ath);
    cudaGetSymbolAddress((void**)&atm, g_Atm);
    cudaGetSymbolAddress((void**)&wqh, g_Wqh);
    cudaGetSymbolAddress((void**)&wqm, g_Wqm);
    cudaGetSymbolAddress((void**)&wkvh, g_Wkvh);
    cudaGetSymbolAddress((void**)&wkvm, g_Wkvm);
    cudaGetSymbolAddress((void**)&woh, g_Woh);
    cudaGetSymbolAddress((void**)&wom, g_Wom);
    cudaGetSymbolAddress((void**)&qh, g_Qh);
    cudaGetSymbolAddress((void**)&qm, g_Qm);
    cudaGetSymbolAddress((void**)&kh, g_Kh);
    cudaGetSymbolAddress((void**)&km, g_Km);
    cudaGetSymbolAddress((void**)&vth, g_Vth);
    cudaGetSymbolAddress((void**)&vtm, g_Vtm);
    cudaGetSymbolAddress((void**)&oh, g_Oh);
    cudaGetSymbolAddress((void**)&om, g_Om);

    cudaFuncSetAttribute(qkv_gemm_kernel,
                         cudaFuncAttributeMaxDynamicSharedMemorySize, GEMM_SMEM);
    cudaFuncSetAttribute(out_gemm_kernel,
                         cudaFuncAttributeMaxDynamicSharedMemorySize, GEMM_SMEM);
    cudaFuncSetAttribute(flash_mma_kernel,
                         cudaFuncAttributeMaxDynamicSharedMemorySize, FLASH_SMEM);

    // 0) pre-split activations, split+transpose weights
    {
        const int nA = Mrows * Fdim / 4;
        asplit_kernel<<<(nA + 255) / 256, 256>>>(attend_from, afh, afm, nA);
        asplit_kernel<<<(nA + 255) / 256, 256>>>(attend_to,   ath, atm, nA);
        wsplit_kernel<<<dim3(32, 32), 256>>>(w_q,   wqh,  wqm,  1024, 1024);
        wsplit_kernel<<<dim3(32, 64), 256>>>(w_kv,  wkvh, wkvm, 1024, 2048);
        wsplit_kernel<<<dim3(32, 32), 256>>>(w_out, woh,  wom,  1024, 1024);
    }

    // 1) merged Q + KV projection (Q/K: 3-MMA, V: 1-MMA)
    qkv_gemm_kernel<<<384, 256, GEMM_SMEM>>>(
        afh, afm, ath, atm, wqh, wqm, wkvh, wkvm, b_q, b_kv,
        qh, qm, kh, km, vth, vtm);

    // 2) flash attention (S: 3-MMA, O: 1-MMA; row s=0 via row0_kernel)
    {
        dim3 grid(Sseq / 128, Hh, Bsz);
        flash_mma_kernel<<<grid, 256, FLASH_SMEM>>>(
            qh, qm, kh, km, vth, oh, om);
    }

    // 2b) exact fix-up for fully-masked row s=0
    {
        dim3 grid(1024, Bsz);
        row0_kernel<<<grid, 256>>>(vth, vtm, oh, om);
    }

    // 3) output projection (1-MMA)
    {
        dim3 grid(Fdim / 256, Mrows / 128);
        out_gemm_kernel<<<grid, 256, GEMM_SMEM>>>(oh, om, woh, wom, b_out, out);
    }
}

// round 16
// speedup vs baseline: 1.4839x; 1.0527x over previous
#include <cuda_runtime.h>
#include <cuda_fp16.h>
#include <math.h>
#include <stdint.h>

// Problem constants (fixed shapes)
constexpr int Bsz  = 2;
constexpr int Sseq = 2048;
constexpr int Fdim = 1024;
constexpr int Hh   = 16;
constexpr int Dh   = 64;
constexpr int Mrows = Bsz * Sseq;   // 4096

// Scratch (device globals, allocation-free). Operands live as fp16 planes:
// hi = fp16(x), mid = fp16(x - hi); hi+mid recovers fp32 to ~2^-22.
// Mid planes exist only where a correction MMA consumes them.
__device__ __half g_Afh[(size_t)Mrows * Fdim];
__device__ __half g_Afm[(size_t)Mrows * Fdim];
__device__ __half g_Ath[(size_t)Mrows * Fdim];
__device__ __half g_Atm[(size_t)Mrows * Fdim];
__device__ __half g_Wqh[(size_t)Fdim * Fdim];      // w_q^T  [n][k]
__device__ __half g_Wqm[(size_t)Fdim * Fdim];
__device__ __half g_Wkvh[(size_t)2 * Fdim * Fdim]; // w_kv^T [n][k]
__device__ __half g_Wkvm[(size_t)2 * Fdim * Fdim]; // only K half read
__device__ __half g_Woh[(size_t)Fdim * Fdim];      // w_out^T [n][k] (hi only)
__device__ __half g_Qh[(size_t)Mrows * Fdim];
__device__ __half g_Qm[(size_t)Mrows * Fdim];
__device__ __half g_Kh[(size_t)Mrows * Fdim];
__device__ __half g_Km[(size_t)Mrows * Fdim];
__device__ __half g_Vth[(size_t)Mrows * Fdim];     // V^T [b][h][d][s]
__device__ __half g_Oh[(size_t)Mrows * Fdim];

// ---------------------------------------------------------------------------
// PTX helpers
// ---------------------------------------------------------------------------
__device__ __forceinline__ void cp_async16(uint32_t saddr, const void* gptr) {
    asm volatile("cp.async.cg.shared.global [%0], [%1], 16;"
                 :: "r"(saddr), "l"(gptr));
}
__device__ __forceinline__ void cp_commit() {
    asm volatile("cp.async.commit_group;");
}
__device__ __forceinline__ void cp_wait0() {
    asm volatile("cp.async.wait_group 0;");
}

__device__ __forceinline__ void mma_f16(
    float& d0, float& d1, float& d2, float& d3,
    uint32_t a0, uint32_t a1, uint32_t a2, uint32_t a3,
    uint32_t b0, uint32_t b1)
{
    asm volatile(
        "mma.sync.aligned.m16n8k16.row.col.f32.f16.f16.f32 "
        "{%0,%1,%2,%3},{%4,%5,%6,%7},{%8,%9},{%0,%1,%2,%3};"
        : "+f"(d0), "+f"(d1), "+f"(d2), "+f"(d3)
        : "r"(a0), "r"(a1), "r"(a2), "r"(a3), "r"(b0), "r"(b1));
}

__device__ __forceinline__ void hsplit(float v, __half& h, __half& m) {
    h = __float2half_rn(v);
    m = __float2half_rn(v - __half2float(h));
}
__device__ __forceinline__ uint32_t hpack(__half lo, __half hi) {
    __half2 t;
    t.x = lo; t.y = hi;
    return *reinterpret_cast<uint32_t*>(&t);
}

// ---------------------------------------------------------------------------
// Pre-pass: split BOTH activations in one launch. grid (4096, 2).
// ---------------------------------------------------------------------------
__global__ __launch_bounds__(256) void asplit2_kernel(
    const float* __restrict__ a, const float* __restrict__ b,
    __half* __restrict__ ahh, __half* __restrict__ ahm,
    __half* __restrict__ bhh, __half* __restrict__ bhm, int n4)
{
    const float* src = blockIdx.y ? b : a;
    __half* hi  = blockIdx.y ? bhh : ahh;
    __half* mid = blockIdx.y ? bhm : ahm;
    const int i = blockIdx.x * 256 + threadIdx.x;
    if (i >= n4) return;
    float4 v = ((const float4*)src)[i];
    __half h0, h1, h2, h3, m0, m1, m2, m3;
    hsplit(v.x, h0, m0); hsplit(v.y, h1, m1);
    hsplit(v.z, h2, m2); hsplit(v.w, h3, m3);
    ((uint2*)hi)[i]  = make_uint2(hpack(h0, h1), hpack(h2, h3));
    ((uint2*)mid)[i] = make_uint2(hpack(m0, m1), hpack(m2, m3));
}

// Pre-pass: split + transpose ALL weights in one launch. grid (32, 128).
//  y <  32 : w_q   -> (Wqh, Wqm)
//  y <  96 : w_kv  -> (Wkvh, Wkvm)
//  else    : w_out -> Woh (hi only; mid never consumed)
__global__ __launch_bounds__(256) void wsplit_all_kernel(
    const float* __restrict__ wq, const float* __restrict__ wkv,
    const float* __restrict__ wo,
    __half* __restrict__ Wqh, __half* __restrict__ Wqm,
    __half* __restrict__ Wkvh, __half* __restrict__ Wkvm,
    __half* __restrict__ Woh)
{
    __shared__ float ts[32][33];
    const int yb = blockIdx.y;
    const float* w;
    __half *th, *tm;
    int N, n0;
    bool write_mid = true;
    if (yb < 32)      { w = wq;  th = Wqh;  tm = Wqm;  N = 1024; n0 = yb * 32; }
    else if (yb < 96) { w = wkv; th = Wkvh; tm = Wkvm; N = 2048; n0 = (yb - 32) * 32; }
    else              { w = wo;  th = Woh;  tm = nullptr; N = 1024; n0 = (yb - 96) * 32;
                        write_mid = false; }
    const int K = 1024;
    const int k0 = blockIdx.x * 32;
    const int tx = threadIdx.x & 31;
    const int ty = threadIdx.x >> 5;
    #pragma unroll
    for (int i = 0; i < 4; i++)
        ts[ty + 8 * i][tx] = w[(size_t)(k0 + ty + 8 * i) * N + n0 + tx];
    __syncthreads();
    #pragma unroll
    for (int i = 0; i < 4; i++) {
        float v = ts[tx][ty + 8 * i];
        __half h, m;
        hsplit(v, h, m);
        const size_t o = (size_t)(n0 + ty + 8 * i) * K + k0 + tx;
        th[o] = h;
        if (write_mid) tm[o] = m;
    }
}

// Row-0 fix: fully-masked row -> uniform softmax -> mean of V rows.
// (Vth hi-only: mean over 2048 averages the fp16 noise to ~1e-5 rel.)
__global__ __launch_bounds__(256) void row0_kernel(
    const __half* __restrict__ Vth, __half* __restrict__ Oh)
{
    __shared__ float red[256];
    const int f = blockIdx.x;
    const int b = blockIdx.y;
    const int h = f >> 6, d = f & 63;
    const size_t base = ((size_t)(b * 16 + h) * 64 + d) * 2048;
    float s = 0.f;
    for (int i = threadIdx.x; i < 2048; i += 256)
        s += __half2float(Vth[base + i]);
    red[threadIdx.x] = s;
    __syncthreads();
    for (int o = 128; o > 0; o >>= 1) {
        if (threadIdx.x < o) red[threadIdx.x] += red[threadIdx.x + o];
        __syncthreads();
    }
    if (threadIdx.x == 0)
        Oh[(size_t)(b * Sseq) * 1024 + f] =
            __float2half_rn(red[0] * (1.f / 2048.f));
}

// ---------------------------------------------------------------------------
// fp16 GEMM core: C[M,N] = A[M,1024] @ W^T[n][k] (+bias via epilogue).
// CTA tile 128x256, BK=32, 256 threads, 8 warps of 64x64 warp tiles,
// 2-stage cp.async pipeline.
// NMMA=3: Am·Bh + Ah·Bm + Ah·Bh (err ~2^-22);  NMMA=1: Ah·Bh (~4e-4).
// ---------------------------------------------------------------------------
constexpr int SW   = 20;                    // words per row (16 data + 4 pad)
constexpr int PLWA = 128 * SW;              // 2560 words per A plane
constexpr int PLWB = 256 * SW;              // 5120 words per B plane
constexpr int STAGE_W = 2 * PLWA + 2 * PLWB;        // 15360 words
constexpr int GEMM_SMEM = 2 * STAGE_W * 4;          // 122880 B

template <int NMMA, typename EPI>
__device__ __forceinline__ void gemm_mainloop(
    const __half* __restrict__ Ah, const __half* __restrict__ Am,
    const __half* __restrict__ Bh, const __half* __restrict__ Bm,
    int m0, int n0, uint32_t* smw, EPI epi)
{
    const uint32_t sbase = (uint32_t)__cvta_generic_to_shared(smw);
    const int tid  = threadIdx.x;
    const int warp = tid >> 5;
    const int lane = tid & 31;
    const int rbase = (warp & 1) * 64;
    const int cbase = (warp >> 1) * 64;
    const int lq  = lane >> 2;
    const int lc  = lane & 3;

    float acc[4][8][4];
    #pragma unroll
    for (int i = 0; i < 4; i++)
        #pragma unroll
        for (int j = 0; j < 8; j++)
            #pragma unroll
            for (int r = 0; r < 4; r++) acc[i][j][r] = 0.f;

    auto load_tile = [&](int kt, int st) {
        const int k0 = kt * 32;
        const uint32_t base = sbase + (uint32_t)(st * STAGE_W) * 4u;
        #pragma unroll
        for (int it = 0; it < 2; it++) {
            const int slot = it * 256 + tid;
            const int row = slot >> 2, c4 = slot & 3;
            const uint32_t so = (uint32_t)(row * SW + c4 * 4) * 4u;
            const size_t ga = (size_t)(m0 + row) * 1024 + k0 + c4 * 8;
            cp_async16(base + so, &Ah[ga]);
            if (NMMA >= 2)
                cp_async16(base + (uint32_t)(PLWA * 4) + so, &Am[ga]);
        }
        #pragma unroll
        for (int it = 0; it < 4; it++) {
            const int slot = it * 256 + tid;
            const int row = slot >> 2, c4 = slot & 3;
            const uint32_t so = (uint32_t)(row * SW + c4 * 4) * 4u;
            const size_t gb = (size_t)(n0 + row) * 1024 + k0 + c4 * 8;
            cp_async16(base + (uint32_t)(2 * PLWA * 4) + so, &Bh[gb]);
            if (NMMA == 3)
                cp_async16(base + (uint32_t)((2 * PLWA + PLWB) * 4) + so, &Bm[gb]);
        }
    };

    load_tile(0, 0);
    cp_commit();

    for (int kt = 0; kt < 32; kt++) {
        cp_wait0();
        __syncthreads();
        if (kt + 1 < 32) { load_tile(kt + 1, (kt + 1) & 1); cp_commit(); }

        const uint32_t* AH = smw + (kt & 1) * STAGE_W;
        const uint32_t* AM = AH + PLWA;
        const uint32_t* BH = AH + 2 * PLWA;
        const uint32_t* BM = AH + 2 * PLWA + PLWB;

        #pragma unroll
        for (int ks = 0; ks < 2; ks++) {
            const int kk2 = ks * 8;
            uint32_t ah[4][4], am[4][4];
            #pragma unroll
            for (int mi = 0; mi < 4; mi++) {
                const int rr = rbase + mi * 16 + lq;
                const int o0 = rr * SW + kk2 + lc;
                const int o1 = (rr + 8) * SW + kk2 + lc;
                ah[mi][0] = AH[o0];
                ah[mi][1] = AH[o1];
                ah[mi][2] = AH[o0 + 4];
                ah[mi][3] = AH[o1 + 4];
                if (NMMA >= 2) {
                    am[mi][0] = AM[o0];
                    am[mi][1] = AM[o1];
                    am[mi][2] = AM[o0 + 4];
                    am[mi][3] = AM[o1 + 4];
                }
            }
            #pragma unroll
            for (int njp = 0; njp < 2; njp++) {
                uint32_t bh[4][2], bm[4][2];
                #pragma unroll
                for (int j = 0; j < 4; j++) {
                    const int cc = cbase + (njp * 4 + j) * 8 + lq;
                    const int o = cc * SW + kk2 + lc;
                    bh[j][0] = BH[o];
                    bh[j][1] = BH[o + 4];
                    if (NMMA == 3) { bm[j][0] = BM[o]; bm[j][1] = BM[o + 4]; }
                }
                #pragma unroll
                for (int mi = 0; mi < 4; mi++)
                    #pragma unroll
                    for (int j = 0; j < 4; j++) {
                        const int nj = njp * 4 + j;
                        if (NMMA >= 2)
                            mma_f16(acc[mi][nj][0], acc[mi][nj][1],
                                    acc[mi][nj][2], acc[mi][nj][3],
                                    am[mi][0], am[mi][1], am[mi][2], am[mi][3],
                                    bh[j][0], bh[j][1]);
                        if (NMMA == 3)
                            mma_f16(acc[mi][nj][0], acc[mi][nj][1],
                                    acc[mi][nj][2], acc[mi][nj][3],
                                    ah[mi][0], ah[mi][1], ah[mi][2], ah[mi][3],
                                    bm[j][0], bm[j][1]);
                        mma_f16(acc[mi][nj][0], acc[mi][nj][1],
                                acc[mi][nj][2], acc[mi][nj][3],
                                ah[mi][0], ah[mi][1], ah[mi][2], ah[mi][3],
                                bh[j][0], bh[j][1]);
                    }
            }
        }
    }
    __syncthreads();
    epi(acc, rbase, cbase, lq, lc);
}

// Merged Q + KV projection. grid.x = 384, heavy-first ordering:
//  bx <  128 : Q  (3-MMA)
//  bx <  256 : K  (3-MMA)
//  else      : V  (1-MMA)  -- cheap tiles land in the last wave.
__global__ __launch_bounds__(256, 1) void qkv_gemm_kernel(
    const __half* __restrict__ Afh, const __half* __restrict__ Afm,
    const __half* __restrict__ Ath, const __half* __restrict__ Atm,
    const __half* __restrict__ Wqh, const __half* __restrict__ Wqm,
    const __half* __restrict__ Wkvh, const __half* __restrict__ Wkvm,
    const float* __restrict__ bq, const float* __restrict__ bkv,
    __half* __restrict__ Qh, __half* __restrict__ Qm,
    __half* __restrict__ Kh, __half* __restrict__ Km,
    __half* __restrict__ Vth)
{
    extern __shared__ uint32_t smw[];
    const int bx = blockIdx.x;
    const int sub = bx & 127;
    const int m0 = (sub >> 2) * 128;
    const int ncol = (sub & 3) * 256;

    if (bx < 256) {
        // Q (bx<128) or K tile, 3-MMA
        const bool isq = (bx < 128);
        const __half* Ah = isq ? Afh : Ath;
        const __half* Am = isq ? Afm : Atm;
        const __half* Bh = isq ? Wqh : Wkvh;
        const __half* Bm = isq ? Wqm : Wkvm;
        const float* bias = isq ? bq : bkv;
        __half* Dh = isq ? Qh : Kh;
        __half* Dm = isq ? Qm : Km;
        gemm_mainloop<3>(Ah, Am, Bh, Bm, m0, ncol, smw,
            [&](float (&acc)[4][8][4], int rbase, int cbase, int lq, int lc) {
                #pragma unroll
                for (int mi = 0; mi < 4; mi++) {
                    const int r0 = m0 + rbase + mi * 16 + lq;
                    #pragma unroll
                    for (int nj = 0; nj < 8; nj++) {
                        const int col = ncol + cbase + nj * 8 + lc * 2;
                        const float b0 = bias[col];
                        const float b1 = bias[col + 1];
                        float v00 = acc[mi][nj][0] + b0;
                        float v01 = acc[mi][nj][1] + b1;
                        float v10 = acc[mi][nj][2] + b0;
                        float v11 = acc[mi][nj][3] + b1;
                        __half h00, h01, h10, h11, q00, q01, q10, q11;
                        hsplit(v00, h00, q00); hsplit(v01, h01, q01);
                        hsplit(v10, h10, q10); hsplit(v11, h11, q11);
                        const size_t o0 = (size_t)r0 * 1024 + col;
                        const size_t o1 = (size_t)(r0 + 8) * 1024 + col;
                        *(uint32_t*)&Dh[o0] = hpack(h00, h01);
                        *(uint32_t*)&Dh[o1] = hpack(h10, h11);
                        *(uint32_t*)&Dm[o0] = hpack(q00, q01);
                        *(uint32_t*)&Dm[o1] = hpack(q10, q11);
                    }
                }
            });
    } else {
        // V tile: 1-MMA, B rows 1024+ncol.., output transposed hi-only
        gemm_mainloop<1>(Ath, Atm, Wkvh, Wkvm, m0, 1024 + ncol, smw,
            [&](float (&acc)[4][8][4], int rbase, int cbase, int lq, int lc) {
                #pragma unroll
                for (int mi = 0; mi < 4; mi++) {
                    const int r0 = m0 + rbase + mi * 16 + lq;
                    #pragma unroll
                    for (int nj = 0; nj < 8; nj++) {
                        const int col = ncol + cbase + nj * 8 + lc * 2;
                        const float b0 = bkv[1024 + col];
                        const float b1 = bkv[1024 + col + 1];
                        float v00 = acc[mi][nj][0] + b0;
                        float v01 = acc[mi][nj][1] + b1;
                        float v10 = acc[mi][nj][2] + b0;
                        float v11 = acc[mi][nj][3] + b1;
                        // V transposed: [b][h][d][s], hi plane only
                        const int h = col >> 6, d = col & 63;
                        const int bl0 = r0 >> 11, s0 = r0 & 2047;
                        const int bl1 = (r0 + 8) >> 11, s1 = (r0 + 8) & 2047;
                        const size_t i00 = ((size_t)(bl0 * 16 + h) * 64 + d) * 2048 + s0;
                        const size_t i10 = ((size_t)(bl1 * 16 + h) * 64 + d) * 2048 + s1;
                        Vth[i00]        = __float2half_rn(v00);
                        Vth[i00 + 2048] = __float2half_rn(v01);
                        Vth[i10]        = __float2half_rn(v10);
                        Vth[i10 + 2048] = __float2half_rn(v11);
                    }
                }
            });
    }
}

// Output projection: out = O @ w_out + b_out (fp32 store). 1-MMA path.
__global__ __launch_bounds__(256, 1) void out_gemm_kernel(
    const __half* __restrict__ Ah, const __half* __restrict__ Bh,
    const float* __restrict__ bias, float* __restrict__ C)
{
    extern __shared__ uint32_t smw[];
    const int m0 = blockIdx.y * 128;
    const int n0 = blockIdx.x * 256;
    gemm_mainloop<1>(Ah, nullptr, Bh, nullptr, m0, n0, smw,
        [&](float (&acc)[4][8][4], int rbase, int cbase, int lq, int lc) {
            #pragma unroll
            for (int mi = 0; mi < 4; mi++) {
                const int r0 = m0 + rbase + mi * 16 + lq;
                #pragma unroll
                for (int nj = 0; nj < 8; nj++) {
                    const int col = n0 + cbase + nj * 8 + lc * 2;
                    const float b0 = bias[col], b1 = bias[col + 1];
                    *(float2*)&C[(size_t)r0 * Fdim + col] =
                        make_float2(acc[mi][nj][0] + b0, acc[mi][nj][1] + b1);
                    *(float2*)&C[(size_t)(r0 + 8) * Fdim + col] =
                        make_float2(acc[mi][nj][2] + b0, acc[mi][nj][3] + b1);
                }
            }
        });
}

// ---------------------------------------------------------------------------
// fp16 flash attention. Br=128, Bc=64, d=64. 8 warps, 16 q-rows each.
// S: 3 MMAs (logit-accurate). O: 1 MMA (P hi x V hi; linear path).
// 3 smem planes (Kh, Km, Vh), double-buffered. Output Oh only (hi plane).
// Mask: z >= s -> -1e12f. CTA t: 2t+2 tiles; row 0 via row0_kernel.
// ---------------------------------------------------------------------------
constexpr int FST = 36;
constexpr int FTW = 64 * FST;
constexpr int FLASH_SMEM = 6 * FTW * 4;   // 3 planes x 2 stages = 55296 B

__global__ __launch_bounds__(256) void flash_mma_kernel(
    const __half* __restrict__ Qh, const __half* __restrict__ Qm,
    const __half* __restrict__ Kh, const __half* __restrict__ Km,
    const __half* __restrict__ Vth, __half* __restrict__ Oh)
{
    extern __shared__ uint32_t smw[];
    const uint32_t sbase = (uint32_t)__cvta_generic_to_shared(smw);

    const int t = 15 - (int)blockIdx.x;
    const int h = blockIdx.y;
    const int b = blockIdx.z;
    const int tid  = threadIdx.x;
    const int warp = tid >> 5;
    const int lane = tid & 31;
    const int lq  = lane >> 2;
    const int lc  = lane & 3;

    auto plane = [&](int p, int st) { return (uint32_t)((p * 2 + st) * FTW); };

    auto load_kv = [&](int kc, int st) {
        #pragma unroll
        for (int it = 0; it < 2; it++) {
            const int slot = it * 256 + tid;
            const int row = slot >> 3;
            const int c8 = slot & 7;
            const uint32_t so = (uint32_t)(row * FST + c8 * 4) * 4u;
            const size_t gk = (size_t)(b * Sseq + kc * 64 + row) * 1024 + h * 64 + c8 * 8;
            cp_async16(sbase + (plane(0, st)) * 4u + so, &Kh[gk]);
            cp_async16(sbase + (plane(1, st)) * 4u + so, &Km[gk]);
            const size_t gv = ((size_t)(b * 16 + h) * 64 + row) * 2048 + kc * 64 + c8 * 8;
            cp_async16(sbase + (plane(2, st)) * 4u + so, &Vth[gv]);
        }
    };

    load_kv(0, 0);
    cp_commit();

    const uint32_t* Qh32 = (const uint32_t*)Qh;
    const uint32_t* Qm32 = (const uint32_t*)Qm;
    uint32_t qh[4][4], qm[4][4];
    {
        const int qrow = b * Sseq + t * 128 + warp * 16 + lq;
        const size_t qb0 = (size_t)qrow * 512 + h * 32;
        const size_t qb1 = qb0 + 8 * 512;
        #pragma unroll
        for (int ks = 0; ks < 4; ks++) {
            const int o = ks * 8 + lc;
            qh[ks][0] = Qh32[qb0 + o];     qm[ks][0] = Qm32[qb0 + o];
            qh[ks][1] = Qh32[qb1 + o];     qm[ks][1] = Qm32[qb1 + o];
            qh[ks][2] = Qh32[qb0 + o + 4]; qm[ks][2] = Qm32[qb0 + o + 4];
            qh[ks][3] = Qh32[qb1 + o + 4]; qm[ks][3] = Qm32[qb1 + o + 4];
        }
    }

    float oacc[8][4];
    #pragma unroll
    for (int nt = 0; nt < 8; nt++)
        #pragma unroll
        for (int r = 0; r < 4; r++) oacc[nt][r] = 0.f;
    float m0 = -3.0e38f, m1 = -3.0e38f, l0 = 0.f, l1 = 0.f;

    const int row0 = t * 128 + warp * 16 + lq;
    const int row1 = row0 + 8;
    const int nkc = 2 * t + 2;

    for (int kc = 0; kc < nkc; kc++) {
        cp_wait0();
        __syncthreads();
        if (kc + 1 < nkc) { load_kv(kc + 1, (kc + 1) & 1); cp_commit(); }

        const int st = kc & 1;
        const uint32_t* KH = smw + plane(0, st);
        const uint32_t* KM = smw + plane(1, st);
        const uint32_t* VH = smw + plane(2, st);

        float sacc[8][4];
        #pragma unroll
        for (int nt = 0; nt < 8; nt++)
            #pragma unroll
            for (int r = 0; r < 4; r++) sacc[nt][r] = 0.f;

        #pragma unroll
        for (int ks = 0; ks < 4; ks++) {
            #pragma unroll
            for (int nt = 0; nt < 8; nt++) {
                const int ko = (nt * 8 + lq) * FST + ks * 8 + lc;
                const uint32_t bh0 = KH[ko], bh1 = KH[ko + 4];
                const uint32_t bm0 = KM[ko], bm1 = KM[ko + 4];
                mma_f16(sacc[nt][0], sacc[nt][1], sacc[nt][2], sacc[nt][3],
                        qm[ks][0], qm[ks][1], qm[ks][2], qm[ks][3], bh0, bh1);
                mma_f16(sacc[nt][0], sacc[nt][1], sacc[nt][2], sacc[nt][3],
                        qh[ks][0], qh[ks][1], qh[ks][2], qh[ks][3], bm0, bm1);
                mma_f16(sacc[nt][0], sacc[nt][1], sacc[nt][2], sacc[nt][3],
                        qh[ks][0], qh[ks][1], qh[ks][2], qh[ks][3], bh0, bh1);
            }
        }

        #pragma unroll
        for (int nt = 0; nt < 8; nt++) {
            const int cb = kc * 64 + nt * 8 + 2 * lc;
            if (cb     >= row0) sacc[nt][0] = -1.0e12f;
            if (cb + 1 >= row0) sacc[nt][1] = -1.0e12f;
            if (cb     >= row1) sacc[nt][2] = -1.0e12f;
            if (cb + 1 >= row1) sacc[nt][3] = -1.0e12f;
        }

        float mt0 = -3.0e38f, mt1 = -3.0e38f;
        #pragma unroll
        for (int nt = 0; nt < 8; nt++) {
            mt0 = fmaxf(mt0, fmaxf(sacc[nt][0], sacc[nt][1]));
            mt1 = fmaxf(mt1, fmaxf(sacc[nt][2], sacc[nt][3]));
        }
        mt0 = fmaxf(mt0, __shfl_xor_sync(0xffffffffu, mt0, 1));
        mt0 = fmaxf(mt0, __shfl_xor_sync(0xffffffffu, mt0, 2));
        mt1 = fmaxf(mt1, __shfl_xor_sync(0xffffffffu, mt1, 1));
        mt1 = fmaxf(mt1, __shfl_xor_sync(0xffffffffu, mt1, 2));
        const float mn0 = fmaxf(m0, mt0);
        const float mn1 = fmaxf(m1, mt1);
        const float sc0 = __expf(m0 - mn0);
        const float sc1 = __expf(m1 - mn1);
        float ls0 = 0.f, ls1 = 0.f;
        #pragma unroll
        for (int nt = 0; nt < 8; nt++) {
            sacc[nt][0] = __expf(sacc[nt][0] - mn0);
            sacc[nt][1] = __expf(sacc[nt][1] - mn0);
            sacc[nt][2] = __expf(sacc[nt][2] - mn1);
            sacc[nt][3] = __expf(sacc[nt][3] - mn1);
            ls0 += sacc[nt][0] + sacc[nt][1];
            ls1 += sacc[nt][2] + sacc[nt][3];
        }
        l0 = l0 * sc0 + ls0;
        l1 = l1 * sc1 + ls1;
        m0 = mn0; m1 = mn1;
        #pragma unroll
        for (int nt = 0; nt < 8; nt++) {
            oacc[nt][0] *= sc0; oacc[nt][1] *= sc0;
            oacc[nt][2] *= sc1; oacc[nt][3] *= sc1;
        }

        // O += P_hi @ V_hi (single MMA; linear path)
        #pragma unroll
        for (int ks = 0; ks < 4; ks++) {
            const uint32_t pah0 = hpack(__float2half_rn(sacc[2 * ks][0]),
                                        __float2half_rn(sacc[2 * ks][1]));
            const uint32_t pah1 = hpack(__float2half_rn(sacc[2 * ks][2]),
                                        __float2half_rn(sacc[2 * ks][3]));
            const uint32_t pah2 = hpack(__float2half_rn(sacc[2 * ks + 1][0]),
                                        __float2half_rn(sacc[2 * ks + 1][1]));
            const uint32_t pah3 = hpack(__float2half_rn(sacc[2 * ks + 1][2]),
                                        __float2half_rn(sacc[2 * ks + 1][3]));
            #pragma unroll
            for (int nt = 0; nt < 8; nt++) {
                const int vo = (nt * 8 + lq) * FST + ks * 8 + lc;
                const uint32_t vh0 = VH[vo], vh1 = VH[vo + 4];
                mma_f16(oacc[nt][0], oacc[nt][1], oacc[nt][2], oacc[nt][3],
                        pah0, pah1, pah2, pah3, vh0, vh1);
            }
        }
    }

    l0 += __shfl_xor_sync(0xffffffffu, l0, 1);
    l0 += __shfl_xor_sync(0xffffffffu, l0, 2);
    l1 += __shfl_xor_sync(0xffffffffu, l1, 1);
    l1 += __shfl_xor_sync(0xffffffffu, l1, 2);
    const float inv0 = 1.f / l0;
    const float inv1 = 1.f / l1;

    const size_t ob = ((size_t)(b * Sseq + t * 128 + warp * 16 + lq)) * 1024 + h * 64;
    #pragma unroll
    for (int nt = 0; nt < 8; nt++) {
        const int cb = nt * 8 + 2 * lc;
        *(uint32_t*)&Oh[ob + cb] =
            hpack(__float2half_rn(oacc[nt][0] * inv0),
                  __float2half_rn(oacc[nt][1] * inv0));
        *(uint32_t*)&Oh[ob + 8 * 1024 + cb] =
            hpack(__float2half_rn(oacc[nt][2] * inv1),
                  __float2half_rn(oacc[nt][3] * inv1));
    }
}

// ---------------------------------------------------------------------------
extern "C" void kernel_launch(void* const* d_in, const int* in_sizes, int n_in,
                              void* d_out, int out_size)
{
    (void)in_sizes; (void)n_in; (void)out_size;
    const float* attend_from = (const float*)d_in[0];
    const float* attend_to   = (const float*)d_in[1];
    const float* w_q   = (const float*)d_in[2];
    const float* b_q   = (const float*)d_in[3];
    const float* w_kv  = (const float*)d_in[4];
    const float* b_kv  = (const float*)d_in[5];
    const float* w_out = (const float*)d_in[6];
    const float* b_out = (const float*)d_in[7];
    float* out = (float*)d_out;

    __half *afh, *afm, *ath, *atm, *wqh, *wqm, *wkvh, *wkvm, *woh;
    __half *qh, *qm, *kh, *km, *vth, *oh;
    cudaGetSymbolAddress((void**)&afh, g_Afh);
    cudaGetSymbolAddress((void**)&afm, g_Afm);
    cudaGetSymbolAddress((void**)&ath, g_Ath);
    cudaGetSymbolAddress((void**)&atm, g_Atm);
    cudaGetSymbolAddress((void**)&wqh, g_Wqh);
    cudaGetSymbolAddress((void**)&wqm, g_Wqm);
    cudaGetSymbolAddress((void**)&wkvh, g_Wkvh);
    cudaGetSymbolAddress((void**)&wkvm, g_Wkvm);
    cudaGetSymbolAddress((void**)&woh, g_Woh);
    cudaGetSymbolAddress((void**)&qh, g_Qh);
    cudaGetSymbolAddress((void**)&qm, g_Qm);
    cudaGetSymbolAddress((void**)&kh, g_Kh);
    cudaGetSymbolAddress((void**)&km, g_Km);
    cudaGetSymbolAddress((void**)&vth, g_Vth);
    cudaGetSymbolAddress((void**)&oh, g_Oh);

    cudaFuncSetAttribute(qkv_gemm_kernel,
                         cudaFuncAttributeMaxDynamicSharedMemorySize, GEMM_SMEM);
    cudaFuncSetAttribute(out_gemm_kernel,
                         cudaFuncAttributeMaxDynamicSharedMemorySize, GEMM_SMEM);
    cudaFuncSetAttribute(flash_mma_kernel,
                         cudaFuncAttributeMaxDynamicSharedMemorySize, FLASH_SMEM);

    // 0) pre-split: activations (1 launch) + all weights (1 launch)
    {
        const int nA = Mrows * Fdim / 4;
        dim3 ga((nA + 255) / 256, 2);
        asplit2_kernel<<<ga, 256>>>(attend_from, attend_to,
                                    afh, afm, ath, atm, nA);
        dim3 gw(32, 128);
        wsplit_all_kernel<<<gw, 256>>>(w_q, w_kv, w_out,
                                       wqh, wqm, wkvh, wkvm, woh);
    }

    // 1) merged Q + KV projection (Q/K: 3-MMA first, V: 1-MMA last)
    qkv_gemm_kernel<<<384, 256, GEMM_SMEM>>>(
        afh, afm, ath, atm, wqh, wqm, wkvh, wkvm, b_q, b_kv,
        qh, qm, kh, km, vth);

    // 2) flash attention (S: 3-MMA, O: 1-MMA; row s=0 via row0_kernel)
    {
        dim3 grid(Sseq / 128, Hh, Bsz);
        flash_mma_kernel<<<grid, 256, FLASH_SMEM>>>(
            qh, qm, kh, km, vth, oh);
    }

    // 2b) exact fix-up for fully-masked row s=0
    {
        dim3 grid(1024, Bsz);
        row0_kernel<<<grid, 256>>>(vth, oh);
    }

    // 3) output projection (1-MMA)
    {
        dim3 grid(Fdim / 256, Mrows / 128);
        out_gemm_kernel<<<grid, 256, GEMM_SMEM>>>(oh, woh, b_out, out);
    }
}